// round 10
// baseline (speedup 1.0000x reference)
#include <cuda_runtime.h>
#include <math.h>

#define Bn 2
#define Tt 4
#define NC 3
#define NK 16
#define Hh 180
#define Ww 320
#define HW (Hh*Ww)
#define CIN_D (Tt*NK)   // 64
#define OUT_C 48
#define SCALE 4

#define LTW 64
#define LTH 16
#define SPW 72
#define SPH 18
#define SPA (SPH*SPW)
#define SPF (SPH*18)

// deform patch: gx in [bx-4, bx+36), gy in [by-4, by+12)
#define DPW 40
#define DPH 16
#define DPP (DPH*DPW)    // 640 positions; stored interleaved [pos][4ch]

typedef unsigned long long ull;

// Scratch (no cudaMalloc allowed)
__device__ float g_hs[Bn*CIN_D*HW];
__device__ float g_c[Bn*NK*HW];
__device__ float g_om[Bn*27*HW];
__device__ float g_def[Bn*NK*HW];

__device__ __forceinline__ float sig_(float v) {
    return __fdividef(1.f, 1.f + __expf(-v));
}
__device__ __forceinline__ float tanh_(float v) {
    float e = __expf(2.f * v);
    return 1.f - __fdividef(2.f, e + 1.f);
}

// ---- packed f32x2 helpers ----
__device__ __forceinline__ ull pack2(float lo, float hi) {
    ull r;
    asm("mov.b64 %0, {%1, %2};" : "=l"(r) : "f"(lo), "f"(hi));
    return r;
}
__device__ __forceinline__ void ffma2(ull& d, ull a, ull b) {
    asm("fma.rn.f32x2 %0, %1, %2, %0;" : "+l"(d) : "l"(a), "l"(b));
}
__device__ __forceinline__ float2 unpack2(ull v) {
    float2 f;
    asm("mov.b64 {%0, %1}, %2;" : "=f"(f.x), "=f"(f.y) : "l"(v));
    return f;
}

__device__ __forceinline__ void cp_async16(float* dst_smem, const float* src) {
    unsigned d = (unsigned)__cvta_generic_to_shared(dst_smem);
    asm volatile("cp.async.cg.shared.global [%0], [%1], 16;" :: "r"(d), "l"(src));
}
__device__ __forceinline__ void cp_async4(float* dst_smem, const float* src) {
    unsigned d = (unsigned)__cvta_generic_to_shared(dst_smem);
    asm volatile("cp.async.ca.shared.global [%0], [%1], 4;" :: "r"(d), "l"(src));
}
#define CP_COMMIT() asm volatile("cp.async.commit_group;" ::: "memory")
#define CP_WAIT0()  asm volatile("cp.async.wait_group 0;" ::: "memory")

// stage one conv patch (gx in [bx-4, bx+68)) with 16B cp.async
__device__ __forceinline__ void stage_patch16(float* dst, const float* src,
                                              int bx, int by, int tid)
{
    #pragma unroll
    for (int i = tid; i < SPF; i += 256) {
        int pr = i / 18, f = i - pr * 18;
        int gy = by - 1 + pr;
        int gxf = bx - 4 + f * 4;
        float* d = dst + pr * SPW + f * 4;
        if (gy >= 0 && gy < Hh && gxf >= 0 && gxf + 4 <= Ww)
            cp_async16(d, src + gy * Ww + gxf);
        else
            *(float4*)d = make_float4(0.f, 0.f, 0.f, 0.f);
    }
}

// stage 4 channels of the deform patch, channel-interleaved [pos][4]
__device__ __forceinline__ void stage_dpatch4(float* dst, const float* src0,
                                              int bx, int by, int tid)
{
    for (int i = tid; i < DPP * 4; i += 256) {
        int pos = i >> 2, cc = i & 3;
        int pr = pos / DPW, pc = pos - pr * DPW;
        int gy = by - 4 + pr;
        int gx = bx - 4 + pc;
        if (gy >= 0 && gy < Hh && gx >= 0 && gx < Ww)
            cp_async4(dst + i, src0 + (size_t)cc * HW + gy * Ww + gx);
        else
            dst[i] = 0.f;
    }
}

// one channel's 3x3 conv; acc2[q][px] = outputs (2q,2q+1) at pixel px.
template<int NQ>
__device__ __forceinline__ void conv_accum_p(ull acc2[][4], const float* patch,
                                             const float* wc, int tx, int ty)
{
    #pragma unroll
    for (int tr = 0; tr < 3; tr++) {
        const float2* rp = (const float2*)(patch + (ty + tr) * SPW + tx * 4 + 2);
        float2 a = rp[0], b = rp[1], c = rp[2], d = rp[3];
        float v[6] = {a.y, b.x, b.y, c.x, c.y, d.x};
        ull vv[6];
        #pragma unroll
        for (int j = 0; j < 6; j++) vv[j] = pack2(v[j], v[j]);
        #pragma unroll
        for (int tc = 0; tc < 3; tc++) {
            const ulonglong2* w2 = (const ulonglong2*)(wc + (tr * 3 + tc) * 16);
            ulonglong2 wa = w2[0], wb = w2[1], wcq = w2[2], wd = w2[3];
            ull wp[8] = {wa.x, wa.y, wb.x, wb.y, wcq.x, wcq.y, wd.x, wd.y};
            #pragma unroll
            for (int q = 0; q < NQ; q++) {
                #pragma unroll
                for (int px = 0; px < 4; px++)
                    ffma2(acc2[q][px], vv[tc + px], wp[q]);
            }
        }
    }
}

// ---------------------------------------------------------------------------
// ConvLSTM step. (unchanged — best known)
// ---------------------------------------------------------------------------
__global__ __launch_bounds__(256, 2)
void lstm_step_kernel(const float* __restrict__ X,
                      const float* __restrict__ lw,
                      const float* __restrict__ lb,
                      const float* __restrict__ Wci,
                      const float* __restrict__ Wcf,
                      const float* __restrict__ Wco,
                      int t)
{
    __shared__ __align__(16) float sw[19 * 9 * 16];
    __shared__ __align__(16) float sp[2][4 * SPA];
    __shared__ float sb[16];

    const int tx = threadIdx.x, ty = threadIdx.y;
    const int tid = ty * 16 + tx;
    const int bz = blockIdx.z;
    const int b = bz >> 2, kg = bz & 3;
    const int bx = blockIdx.x * LTW, by = blockIdx.y * LTH;
    const int x0 = bx + tx * 4, y = by + ty;

    for (int i = tid; i < 19 * 144; i += 256) {
        int lo = i / 171, rest = i - lo * 171;
        int row = (lo >> 2) * NK + kg * 4 + (lo & 3);
        sw[rest * 16 + lo] = lw[row * 171 + rest];
    }
    if (tid < 16)
        sb[tid] = lb[(tid >> 2) * NK + kg * 4 + (tid & 3)];

    const int ncin = (t == 0) ? NC : (NC + NK);
    const int nb = (ncin + 3) >> 2;

    #define LSTM_SRC(c) ((c) < NC \
        ? (X + (((size_t)b * Tt + t) * NC + (c)) * HW) \
        : (g_hs + ((size_t)b * CIN_D + (t - 1) * NK + ((c) - NC)) * HW))

    #pragma unroll
    for (int cc = 0; cc < 4; cc++)
        if (cc < ncin) stage_patch16(sp[0] + cc * SPA, LSTM_SRC(cc), bx, by, tid);
    CP_COMMIT();

    __syncthreads();

    ull acc2[8][4];
    #pragma unroll
    for (int q = 0; q < 8; q++) {
        ull bv = pack2(sb[2*q], sb[2*q+1]);
        #pragma unroll
        for (int px = 0; px < 4; px++) acc2[q][px] = bv;
    }

    for (int cb = 0; cb < nb; cb++) {
        int cur = cb & 1;
        CP_WAIT0();
        __syncthreads();
        if (cb + 1 < nb) {
            int cn = (cb + 1) * 4;
            #pragma unroll
            for (int cc = 0; cc < 4; cc++)
                if (cn + cc < ncin)
                    stage_patch16(sp[cur ^ 1] + cc * SPA, LSTM_SRC(cn + cc), bx, by, tid);
        }
        CP_COMMIT();
        int c0 = cb * 4;
        #pragma unroll
        for (int cc = 0; cc < 4; cc++)
            if (c0 + cc < ncin)
                conv_accum_p<8>(acc2, sp[cur] + cc * SPA, sw + (c0 + cc) * 144, tx, ty);
    }
    #undef LSTM_SRC

    if (y < Hh) {
        const int p = y * Ww + x0;
        float accf[16][4];
        #pragma unroll
        for (int q = 0; q < 8; q++) {
            #pragma unroll
            for (int px = 0; px < 4; px++) {
                float2 u = unpack2(acc2[q][px]);
                accf[2*q][px] = u.x;
                accf[2*q+1][px] = u.y;
            }
        }
        #pragma unroll
        for (int kk = 0; kk < 4; kk++) {
            int k = kg * 4 + kk;
            float ci4[4], cf4[4], co4[4], cp4[4], cn4[4], h4[4];
            *(float4*)ci4 = *(const float4*)(Wci + k * HW + p);
            *(float4*)cf4 = *(const float4*)(Wcf + k * HW + p);
            *(float4*)co4 = *(const float4*)(Wco + k * HW + p);
            if (t == 0) {
                #pragma unroll
                for (int px = 0; px < 4; px++) cp4[px] = 0.f;
            } else {
                *(float4*)cp4 = *(const float4*)(g_c + ((size_t)b * NK + k) * HW + p);
            }
            #pragma unroll
            for (int px = 0; px < 4; px++) {
                float cprev = cp4[px];
                float i_ = sig_(accf[kk][px]      + ci4[px] * cprev);
                float f_ = sig_(accf[4 + kk][px]  + cf4[px] * cprev);
                float cn = f_ * cprev + i_ * tanh_(accf[8 + kk][px]);
                float o_ = sig_(accf[12 + kk][px] + co4[px] * cn);
                cn4[px] = cn;
                h4[px] = o_ * tanh_(cn);
            }
            *(float4*)(g_c + ((size_t)b * NK + k) * HW + p) = *(float4*)cn4;
            *(float4*)(g_hs + ((size_t)b * CIN_D + t * NK + k) * HW + p) = *(float4*)h4;
        }
    }
}

// ---------------------------------------------------------------------------
// Offset+mask conv 64 -> 27 (16+11 split, as in the 549.6us best).
// ---------------------------------------------------------------------------
__global__ __launch_bounds__(256, 2)
void offmask_kernel(const float* __restrict__ off_w,
                    const float* __restrict__ off_b,
                    const float* __restrict__ mod_w,
                    const float* __restrict__ mod_b)
{
    __shared__ __align__(16) float sw[16 * 576];
    __shared__ __align__(16) float sp[2][4 * SPA];
    __shared__ float sb[16];

    const int tx = threadIdx.x, ty = threadIdx.y;
    const int tid = ty * 16 + tx;
    const int bz = blockIdx.z;
    const int b = bz >> 1, half = bz & 1;
    const int base = half * 16;
    const int count = half ? 11 : 16;
    const int bx = blockIdx.x * LTW, by = blockIdx.y * LTH;
    const int x0 = bx + tx * 4, y = by + ty;

    for (int i = tid; i < 16 * 576; i += 256) {
        int lo = i / 576, rest = i - lo * 576;
        int oc = base + lo;
        float v = 0.f;
        if (oc < 18) v = off_w[(size_t)oc * 576 + rest];
        else if (oc < 27) v = mod_w[(size_t)(oc - 18) * 576 + rest];
        sw[rest * 16 + lo] = v;
    }
    if (tid < 16) {
        int oc = base + tid;
        sb[tid] = (oc < 18) ? off_b[oc] : (oc < 27 ? mod_b[oc - 18] : 0.f);
    }

    const float* xb = g_hs + (size_t)b * CIN_D * HW;

    #pragma unroll
    for (int cc = 0; cc < 4; cc++)
        stage_patch16(sp[0] + cc * SPA, xb + (size_t)cc * HW, bx, by, tid);
    CP_COMMIT();

    __syncthreads();

    ull acc2[8][4];
    #pragma unroll
    for (int q = 0; q < 8; q++) {
        ull bv = pack2(sb[2*q], sb[2*q+1]);
        #pragma unroll
        for (int px = 0; px < 4; px++) acc2[q][px] = bv;
    }

    for (int cb = 0; cb < 16; cb++) {
        int cur = cb & 1;
        CP_WAIT0();
        __syncthreads();
        if (cb + 1 < 16) {
            int cn = (cb + 1) * 4;
            #pragma unroll
            for (int cc = 0; cc < 4; cc++)
                stage_patch16(sp[cur ^ 1] + cc * SPA, xb + (size_t)(cn + cc) * HW, bx, by, tid);
        }
        CP_COMMIT();
        int c0 = cb * 4;
        #pragma unroll
        for (int cc = 0; cc < 4; cc++)
            conv_accum_p<8>(acc2, sp[cur] + cc * SPA, sw + (c0 + cc) * 144, tx, ty);
    }

    if (y < Hh) {
        const int p = y * Ww + x0;
        #pragma unroll
        for (int lo = 0; lo < 16; lo++) {
            if (lo >= count) break;
            int oc = base + lo;
            float o4[4];
            #pragma unroll
            for (int px = 0; px < 4; px++) {
                float2 u = unpack2(acc2[lo >> 1][px]);
                o4[px] = (lo & 1) ? u.y : u.x;
            }
            if (oc >= 18) {
                #pragma unroll
                for (int px = 0; px < 4; px++) o4[px] = 2.f * sig_(o4[px]);
            }
            *(float4*)(g_om + ((size_t)b * 27 + oc) * HW + p) = *(float4*)o4;
        }
    }
}

// ---------------------------------------------------------------------------
// Modulated deformable conv — channel-interleaved patch, float4 sampling.
// block (32,8); per-batch patch [DPP][4ch]; cp.async CH=4 pipeline.
// ---------------------------------------------------------------------------
__global__ __launch_bounds__(256, 2)
void deform_kernel(const float* __restrict__ def_w,
                   const float* __restrict__ def_b)
{
    __shared__ __align__(16) float swd[NK * CIN_D * 9];
    __shared__ __align__(16) float dp[2][DPP * 4];
    __shared__ float sb[NK];

    const int bx = blockIdx.x * 32, by = blockIdx.y * 8;
    const int b = blockIdx.z;
    const int tx = threadIdx.x, ty = threadIdx.y;
    const int tid = ty * 32 + tx;

    for (int i = tid; i < NK * CIN_D * 9; i += 256) {
        int o = i / 576, rest = i - o * 576;
        swd[rest * 16 + o] = def_w[i];
    }
    if (tid < NK) sb[tid] = def_b[tid];

    const int x = bx + tx, y = by + ty;
    const bool validpx = (y < Hh);
    const int yl = validpx ? y : (Hh - 1);
    const int pl = yl * Ww + x;

    const float* xb = g_hs + (size_t)b * CIN_D * HW;
    const float* om = g_om + (size_t)b * 27 * HW;

    // per-pixel per-tap precompute
    float w0_[9], w1_[9], w2_[9], w3_[9];
    int so_[9];
    bool fastAll = true;
    #pragma unroll
    for (int j = 0; j < 9; j++) {
        int ky = j / 3, kx = j - ky * 3;
        float dy = om[(2 * j) * HW + pl];
        float dx = om[(2 * j + 1) * HW + pl];
        float m  = om[(18 + j) * HW + pl];
        float py = (float)(y - 1 + ky) + dy;
        float px_ = (float)(x - 1 + kx) + dx;
        float y0f = floorf(py), x0f = floorf(px_);
        float wy = py - y0f, wx = px_ - x0f;
        int y0 = (int)y0f, x0 = (int)x0f;
        float vy0 = (y0 >= 0 && y0 < Hh) ? 1.f : 0.f;
        float vy1 = (y0 + 1 >= 0 && y0 + 1 < Hh) ? 1.f : 0.f;
        float vx0 = (x0 >= 0 && x0 < Ww) ? 1.f : 0.f;
        float vx1 = (x0 + 1 >= 0 && x0 + 1 < Ww) ? 1.f : 0.f;
        w0_[j] = (1.f - wy) * (1.f - wx) * vy0 * vx0 * m;
        w1_[j] = (1.f - wy) * wx         * vy0 * vx1 * m;
        w2_[j] = wy * (1.f - wx)         * vy1 * vx0 * m;
        w3_[j] = wy * wx                 * vy1 * vx1 * m;
        bool f = (x0 >= bx - 4) && (x0 + 1 <= bx + 35)
              && (y0 >= by - 4) && (y0 + 1 <= by + 11);
        so_[j] = (y0 - (by - 4)) * DPW + (x0 - (bx - 4));
        fastAll = fastAll && f;
    }

    // prologue: stage channels 0..3 interleaved
    stage_dpatch4(dp[0], xb, bx, by, tid);
    CP_COMMIT();
    __syncthreads();   // sb/swd visible

    ull acc2[8];
    #pragma unroll
    for (int q = 0; q < 8; q++) acc2[q] = pack2(sb[2*q], sb[2*q+1]);

    for (int cb = 0; cb < 16; cb++) {
        int cur = cb & 1;
        CP_WAIT0();
        __syncthreads();
        if (cb + 1 < 16) {
            stage_dpatch4(dp[cur ^ 1], xb + (size_t)(cb + 1) * 4 * HW, bx, by, tid);
        }
        CP_COMMIT();
        int c0 = cb * 4;
        if (fastAll) {
            const float4* P4 = (const float4*)(dp[cur]);
            #pragma unroll
            for (int j = 0; j < 9; j++) {
                int s0 = so_[j];
                float4 c00 = P4[s0],       c01 = P4[s0 + 1];
                float4 c10 = P4[s0 + DPW], c11 = P4[s0 + DPW + 1];
                float w0 = w0_[j], w1 = w1_[j], w2 = w2_[j], w3 = w3_[j];
                float4 s4;
                s4.x = w0 * c00.x + w1 * c01.x + w2 * c10.x + w3 * c11.x;
                s4.y = w0 * c00.y + w1 * c01.y + w2 * c10.y + w3 * c11.y;
                s4.z = w0 * c00.z + w1 * c01.z + w2 * c10.z + w3 * c11.z;
                s4.w = w0 * c00.w + w1 * c01.w + w2 * c10.w + w3 * c11.w;
                float sv[4] = {s4.x, s4.y, s4.z, s4.w};
                #pragma unroll
                for (int cc = 0; cc < 4; cc++) {
                    ull ss = pack2(sv[cc], sv[cc]);
                    const ulonglong2* w2v =
                        (const ulonglong2*)(swd + ((c0 + cc) * 9 + j) * 16);
                    ulonglong2 wa = w2v[0], wb = w2v[1], wc2 = w2v[2], wd = w2v[3];
                    ffma2(acc2[0], ss, wa.x); ffma2(acc2[1], ss, wa.y);
                    ffma2(acc2[2], ss, wb.x); ffma2(acc2[3], ss, wb.y);
                    ffma2(acc2[4], ss, wc2.x); ffma2(acc2[5], ss, wc2.y);
                    ffma2(acc2[6], ss, wd.x); ffma2(acc2[7], ss, wd.y);
                }
            }
        } else {
            // slow fallback: original clipped global-gather path (rare)
            for (int cc = 0; cc < 4; cc++) {
                int c = c0 + cc;
                const float* pc_ = xb + (size_t)c * HW;
                for (int j = 0; j < 9; j++) {
                    int ky = j / 3, kx = j - ky * 3;
                    float dy = om[(2 * j) * HW + pl];
                    float dx = om[(2 * j + 1) * HW + pl];
                    float m  = om[(18 + j) * HW + pl];
                    float py = (float)(y - 1 + ky) + dy;
                    float px_ = (float)(x - 1 + kx) + dx;
                    float y0f = floorf(py), x0f = floorf(px_);
                    float wy = py - y0f, wx = px_ - x0f;
                    int y0 = (int)y0f, x0 = (int)x0f;
                    float vy0 = (y0 >= 0 && y0 < Hh) ? 1.f : 0.f;
                    float vy1 = (y0 + 1 >= 0 && y0 + 1 < Hh) ? 1.f : 0.f;
                    float vx0 = (x0 >= 0 && x0 < Ww) ? 1.f : 0.f;
                    float vx1 = (x0 + 1 >= 0 && x0 + 1 < Ww) ? 1.f : 0.f;
                    int y0c = min(max(y0, 0), Hh - 1), y1c = min(max(y0 + 1, 0), Hh - 1);
                    int x0c = min(max(x0, 0), Ww - 1), x1c = min(max(x0 + 1, 0), Ww - 1);
                    float s = (1.f - wy) * (1.f - wx) * vy0 * vx0 * m * pc_[y0c * Ww + x0c]
                            + (1.f - wy) * wx         * vy0 * vx1 * m * pc_[y0c * Ww + x1c]
                            + wy * (1.f - wx)         * vy1 * vx0 * m * pc_[y1c * Ww + x0c]
                            + wy * wx                 * vy1 * vx1 * m * pc_[y1c * Ww + x1c];
                    ull ss = pack2(s, s);
                    const ulonglong2* w2v = (const ulonglong2*)(swd + (c * 9 + j) * 16);
                    ulonglong2 wa = w2v[0], wb = w2v[1], wc2 = w2v[2], wd = w2v[3];
                    ffma2(acc2[0], ss, wa.x); ffma2(acc2[1], ss, wa.y);
                    ffma2(acc2[2], ss, wb.x); ffma2(acc2[3], ss, wb.y);
                    ffma2(acc2[4], ss, wc2.x); ffma2(acc2[5], ss, wc2.y);
                    ffma2(acc2[6], ss, wd.x); ffma2(acc2[7], ss, wd.y);
                }
            }
        }
    }

    if (validpx) {
        const int p = y * Ww + x;
        #pragma unroll
        for (int q = 0; q < 8; q++) {
            float2 u = unpack2(acc2[q]);
            g_def[((size_t)b * NK + 2*q    ) * HW + p] = u.x;
            g_def[((size_t)b * NK + 2*q + 1) * HW + p] = u.y;
        }
    }
}

// ---------------------------------------------------------------------------
// Output conv 16 -> 48 (3 groups of 16) + pixel shuffle + clip. (unchanged)
// ---------------------------------------------------------------------------
__global__ __launch_bounds__(256, 2)
void outconv_kernel(const float* __restrict__ out_w,
                    const float* __restrict__ out_b,
                    float* __restrict__ out)
{
    __shared__ __align__(16) float sw[16 * 144];
    __shared__ __align__(16) float sp[2][4 * SPA];
    __shared__ float sb[16];

    const int tx = threadIdx.x, ty = threadIdx.y;
    const int tid = ty * 16 + tx;
    const int bz = blockIdx.z;
    const int b = bz / 3, g3 = bz - b * 3;
    const int base = g3 * 16;
    const int bx = blockIdx.x * LTW, by = blockIdx.y * LTH;
    const int x0 = bx + tx * 4, y = by + ty;

    for (int i = tid; i < 16 * 144; i += 256) {
        int lo = i / 144, rest = i - lo * 144;
        sw[rest * 16 + lo] = out_w[(size_t)(base + lo) * 144 + rest];
    }
    if (tid < 16) sb[tid] = out_b[base + tid];

    const float* xb = g_def + (size_t)b * NK * HW;

    #pragma unroll
    for (int cc = 0; cc < 4; cc++)
        stage_patch16(sp[0] + cc * SPA, xb + (size_t)cc * HW, bx, by, tid);
    CP_COMMIT();

    __syncthreads();

    ull acc2[8][4];
    #pragma unroll
    for (int q = 0; q < 8; q++) {
        ull bv = pack2(sb[2*q], sb[2*q+1]);
        #pragma unroll
        for (int px = 0; px < 4; px++) acc2[q][px] = bv;
    }

    for (int cb = 0; cb < 4; cb++) {
        int cur = cb & 1;
        CP_WAIT0();
        __syncthreads();
        if (cb + 1 < 4) {
            int cn = (cb + 1) * 4;
            #pragma unroll
            for (int cc = 0; cc < 4; cc++)
                stage_patch16(sp[cur ^ 1] + cc * SPA, xb + (size_t)(cn + cc) * HW, bx, by, tid);
        }
        CP_COMMIT();
        int c0 = cb * 4;
        #pragma unroll
        for (int cc = 0; cc < 4; cc++)
            conv_accum_p<8>(acc2, sp[cur] + cc * SPA, sw + (c0 + cc) * 144, tx, ty);
    }

    if (y < Hh) {
        #pragma unroll
        for (int lo = 0; lo < 16; lo++) {
            int oc = base + lo;
            int cch = oc >> 4, rem = oc & 15;
            int r1 = rem >> 2, r2 = rem & 3;
            #pragma unroll
            for (int px = 0; px < 4; px++) {
                float2 u = unpack2(acc2[lo >> 1][px]);
                float val = (lo & 1) ? u.y : u.x;
                val = fminf(fmaxf(val, 0.f), 255.f);
                size_t oi = (((size_t)b * NC + cch) * (Hh * SCALE) + (y * SCALE + r1))
                            * (size_t)(Ww * SCALE) + ((x0 + px) * SCALE + r2);
                out[oi] = val;
            }
        }
    }
}

// ---------------------------------------------------------------------------
extern "C" void kernel_launch(void* const* d_in, const int* in_sizes, int n_in,
                              void* d_out, int out_size)
{
    const float* X      = (const float*)d_in[0];
    const float* lstm_w = (const float*)d_in[1];
    const float* lstm_b = (const float*)d_in[2];
    const float* W_ci   = (const float*)d_in[3];
    const float* W_cf   = (const float*)d_in[4];
    const float* W_co   = (const float*)d_in[5];
    const float* off_w  = (const float*)d_in[6];
    const float* off_b  = (const float*)d_in[7];
    const float* mod_w  = (const float*)d_in[8];
    const float* mod_b  = (const float*)d_in[9];
    const float* def_w  = (const float*)d_in[10];
    const float* def_b  = (const float*)d_in[11];
    const float* out_w  = (const float*)d_in[12];
    const float* out_b  = (const float*)d_in[13];
    float* out = (float*)d_out;

    dim3 blk16(16, 16);
    dim3 grid_lstm(Ww / LTW, (Hh + LTH - 1) / LTH, Bn * 4);
    dim3 grid_om(Ww / LTW, (Hh + LTH - 1) / LTH, Bn * 2);
    dim3 grid_oc(Ww / LTW, (Hh + LTH - 1) / LTH, Bn * 3);

    for (int t = 0; t < Tt; t++)
        lstm_step_kernel<<<grid_lstm, blk16>>>(X, lstm_w, lstm_b, W_ci, W_cf, W_co, t);

    offmask_kernel<<<grid_om, blk16>>>(off_w, off_b, mod_w, mod_b);

    dim3 blk32(32, 8);
    dim3 grid_def(Ww / 32, (Hh + 7) / 8, Bn);
    deform_kernel<<<grid_def, blk32>>>(def_w, def_b);

    outconv_kernel<<<grid_oc, blk16>>>(out_w, out_b, out);
}

// round 11
// speedup vs baseline: 1.0639x; 1.0639x over previous
#include <cuda_runtime.h>
#include <math.h>

#define Bn 2
#define Tt 4
#define NC 3
#define NK 16
#define Hh 180
#define Ww 320
#define HW (Hh*Ww)
#define CIN_D (Tt*NK)   // 64
#define OUT_C 48
#define SCALE 4

#define LTW 64
#define LTH 16
#define SPW 72
#define SPH 18
#define SPA (SPH*SPW)
#define SPF (SPH*18)

// lstm tile: 64 x 8, 2 px/thread
#define LTH2 8
#define SPH2 10
#define SPA2 (SPH2*SPW)   // 720
#define SPF2 (SPH2*18)    // 180

typedef unsigned long long ull;

// Scratch (no cudaMalloc allowed)
__device__ float g_hs[Bn*CIN_D*HW];
__device__ float g_c[Bn*NK*HW];
__device__ float g_om[Bn*27*HW];
__device__ float g_def[Bn*NK*HW];

__device__ __forceinline__ float sig_(float v) {
    return __fdividef(1.f, 1.f + __expf(-v));
}
__device__ __forceinline__ float tanh_(float v) {
    float e = __expf(2.f * v);
    return 1.f - __fdividef(2.f, e + 1.f);
}

// ---- packed f32x2 helpers ----
__device__ __forceinline__ ull pack2(float lo, float hi) {
    ull r;
    asm("mov.b64 %0, {%1, %2};" : "=l"(r) : "f"(lo), "f"(hi));
    return r;
}
__device__ __forceinline__ void ffma2(ull& d, ull a, ull b) {
    asm("fma.rn.f32x2 %0, %1, %2, %0;" : "+l"(d) : "l"(a), "l"(b));
}
__device__ __forceinline__ float2 unpack2(ull v) {
    float2 f;
    asm("mov.b64 {%0, %1}, %2;" : "=f"(f.x), "=f"(f.y) : "l"(v));
    return f;
}

__device__ __forceinline__ void cp_async16(float* dst_smem, const float* src) {
    unsigned d = (unsigned)__cvta_generic_to_shared(dst_smem);
    asm volatile("cp.async.cg.shared.global [%0], [%1], 16;" :: "r"(d), "l"(src));
}
#define CP_COMMIT() asm volatile("cp.async.commit_group;" ::: "memory")
#define CP_WAIT0()  asm volatile("cp.async.wait_group 0;" ::: "memory")

// stage one conv patch (gx in [bx-4, bx+68)), 18-row version
__device__ __forceinline__ void stage_patch16(float* dst, const float* src,
                                              int bx, int by, int tid)
{
    #pragma unroll
    for (int i = tid; i < SPF; i += 256) {
        int pr = i / 18, f = i - pr * 18;
        int gy = by - 1 + pr;
        int gxf = bx - 4 + f * 4;
        float* d = dst + pr * SPW + f * 4;
        if (gy >= 0 && gy < Hh && gxf >= 0 && gxf + 4 <= Ww)
            cp_async16(d, src + gy * Ww + gxf);
        else
            *(float4*)d = make_float4(0.f, 0.f, 0.f, 0.f);
    }
}

// 10-row version for the lstm tile
__device__ __forceinline__ void stage_patch16_8(float* dst, const float* src,
                                                int bx, int by, int tid)
{
    #pragma unroll
    for (int i = tid; i < SPF2; i += 256) {
        int pr = i / 18, f = i - pr * 18;
        int gy = by - 1 + pr;
        int gxf = bx - 4 + f * 4;
        float* d = dst + pr * SPW + f * 4;
        if (gy >= 0 && gy < Hh && gxf >= 0 && gxf + 4 <= Ww)
            cp_async16(d, src + gy * Ww + gxf);
        else
            *(float4*)d = make_float4(0.f, 0.f, 0.f, 0.f);
    }
}

// one channel's 3x3 conv; acc2[q][px] = outputs (2q,2q+1) at pixel px (4 px).
template<int NQ>
__device__ __forceinline__ void conv_accum_p(ull acc2[][4], const float* patch,
                                             const float* wc, int tx, int ty)
{
    #pragma unroll
    for (int tr = 0; tr < 3; tr++) {
        const float2* rp = (const float2*)(patch + (ty + tr) * SPW + tx * 4 + 2);
        float2 a = rp[0], b = rp[1], c = rp[2], d = rp[3];
        float v[6] = {a.y, b.x, b.y, c.x, c.y, d.x};
        ull vv[6];
        #pragma unroll
        for (int j = 0; j < 6; j++) vv[j] = pack2(v[j], v[j]);
        #pragma unroll
        for (int tc = 0; tc < 3; tc++) {
            const ulonglong2* w2 = (const ulonglong2*)(wc + (tr * 3 + tc) * 16);
            ulonglong2 wa = w2[0], wb = w2[1], wcq = w2[2], wd = w2[3];
            ull wp[8] = {wa.x, wa.y, wb.x, wb.y, wcq.x, wcq.y, wd.x, wd.y};
            #pragma unroll
            for (int q = 0; q < NQ; q++) {
                #pragma unroll
                for (int px = 0; px < 4; px++)
                    ffma2(acc2[q][px], vv[tc + px], wp[q]);
            }
        }
    }
}

// 2-px variant for the lstm kernel (tx in [0,32))
__device__ __forceinline__ void conv_accum_p2(ull acc2[8][2], const float* patch,
                                              const float* wc, int tx, int ty)
{
    #pragma unroll
    for (int tr = 0; tr < 3; tr++) {
        const float2* rp = (const float2*)(patch + (ty + tr) * SPW + tx * 2 + 2);
        float2 a = rp[0], b = rp[1], c = rp[2];
        float v[4] = {a.y, b.x, b.y, c.x};
        ull vv[4];
        #pragma unroll
        for (int j = 0; j < 4; j++) vv[j] = pack2(v[j], v[j]);
        #pragma unroll
        for (int tc = 0; tc < 3; tc++) {
            const ulonglong2* w2 = (const ulonglong2*)(wc + (tr * 3 + tc) * 16);
            ulonglong2 wa = w2[0], wb = w2[1], wcq = w2[2], wd = w2[3];
            ull wp[8] = {wa.x, wa.y, wb.x, wb.y, wcq.x, wcq.y, wd.x, wd.y};
            #pragma unroll
            for (int q = 0; q < 8; q++) {
                #pragma unroll
                for (int px = 0; px < 2; px++)
                    ffma2(acc2[q][px], vv[tc + px], wp[q]);
            }
        }
    }
}

// ---------------------------------------------------------------------------
// ConvLSTM step. block (32,8); thread = 2 px, 16 outputs (4 k x 4 gates).
// 3 CTAs/SM target. blockIdx.z = b*4 + kg.
// ---------------------------------------------------------------------------
__global__ __launch_bounds__(256, 3)
void lstm_step_kernel(const float* __restrict__ X,
                      const float* __restrict__ lw,
                      const float* __restrict__ lb,
                      const float* __restrict__ Wci,
                      const float* __restrict__ Wcf,
                      const float* __restrict__ Wco,
                      int t)
{
    __shared__ __align__(16) float sw[19 * 9 * 16];
    __shared__ __align__(16) float sp[2][4 * SPA2];
    __shared__ float sb[16];

    const int tx = threadIdx.x, ty = threadIdx.y;
    const int tid = ty * 32 + tx;
    const int bz = blockIdx.z;
    const int b = bz >> 2, kg = bz & 3;
    const int bx = blockIdx.x * LTW, by = blockIdx.y * LTH2;
    const int x0 = bx + tx * 2, y = by + ty;

    for (int i = tid; i < 19 * 144; i += 256) {
        int lo = i / 171, rest = i - lo * 171;
        int row = (lo >> 2) * NK + kg * 4 + (lo & 3);
        sw[rest * 16 + lo] = lw[row * 171 + rest];
    }
    if (tid < 16)
        sb[tid] = lb[(tid >> 2) * NK + kg * 4 + (tid & 3)];

    const int ncin = (t == 0) ? NC : (NC + NK);
    const int nb = (ncin + 3) >> 2;

    #define LSTM_SRC(c) ((c) < NC \
        ? (X + (((size_t)b * Tt + t) * NC + (c)) * HW) \
        : (g_hs + ((size_t)b * CIN_D + (t - 1) * NK + ((c) - NC)) * HW))

    #pragma unroll
    for (int cc = 0; cc < 4; cc++)
        if (cc < ncin) stage_patch16_8(sp[0] + cc * SPA2, LSTM_SRC(cc), bx, by, tid);
    CP_COMMIT();

    __syncthreads();   // sb/sw visible

    ull acc2[8][2];
    #pragma unroll
    for (int q = 0; q < 8; q++) {
        ull bv = pack2(sb[2*q], sb[2*q+1]);
        acc2[q][0] = bv; acc2[q][1] = bv;
    }

    for (int cb = 0; cb < nb; cb++) {
        int cur = cb & 1;
        CP_WAIT0();
        __syncthreads();
        if (cb + 1 < nb) {
            int cn = (cb + 1) * 4;
            #pragma unroll
            for (int cc = 0; cc < 4; cc++)
                if (cn + cc < ncin)
                    stage_patch16_8(sp[cur ^ 1] + cc * SPA2, LSTM_SRC(cn + cc), bx, by, tid);
        }
        CP_COMMIT();
        int c0 = cb * 4;
        #pragma unroll
        for (int cc = 0; cc < 4; cc++)
            if (c0 + cc < ncin)
                conv_accum_p2(acc2, sp[cur] + cc * SPA2, sw + (c0 + cc) * 144, tx, ty);
    }
    #undef LSTM_SRC

    if (y < Hh) {
        const int p = y * Ww + x0;
        float accf[16][2];
        #pragma unroll
        for (int q = 0; q < 8; q++) {
            float2 u0 = unpack2(acc2[q][0]);
            float2 u1 = unpack2(acc2[q][1]);
            accf[2*q][0] = u0.x;   accf[2*q][1] = u1.x;
            accf[2*q+1][0] = u0.y; accf[2*q+1][1] = u1.y;
        }
        #pragma unroll
        for (int kk = 0; kk < 4; kk++) {
            int k = kg * 4 + kk;
            float2 ci2 = *(const float2*)(Wci + k * HW + p);
            float2 cf2 = *(const float2*)(Wcf + k * HW + p);
            float2 co2 = *(const float2*)(Wco + k * HW + p);
            float2 cp2 = make_float2(0.f, 0.f);
            if (t != 0)
                cp2 = *(const float2*)(g_c + ((size_t)b * NK + k) * HW + p);
            float ci_[2] = {ci2.x, ci2.y}, cf_[2] = {cf2.x, cf2.y};
            float co_[2] = {co2.x, co2.y}, cp_[2] = {cp2.x, cp2.y};
            float cn_[2], h_[2];
            #pragma unroll
            for (int px = 0; px < 2; px++) {
                float cprev = cp_[px];
                float i_ = sig_(accf[kk][px]      + ci_[px] * cprev);
                float f_ = sig_(accf[4 + kk][px]  + cf_[px] * cprev);
                float cn = f_ * cprev + i_ * tanh_(accf[8 + kk][px]);
                float o_ = sig_(accf[12 + kk][px] + co_[px] * cn);
                cn_[px] = cn;
                h_[px] = o_ * tanh_(cn);
            }
            *(float2*)(g_c + ((size_t)b * NK + k) * HW + p) = make_float2(cn_[0], cn_[1]);
            *(float2*)(g_hs + ((size_t)b * CIN_D + t * NK + k) * HW + p) = make_float2(h_[0], h_[1]);
        }
    }
}

// ---------------------------------------------------------------------------
// Offset+mask conv 64 -> 27 (16+11 split). (R8 best version)
// ---------------------------------------------------------------------------
__global__ __launch_bounds__(256, 2)
void offmask_kernel(const float* __restrict__ off_w,
                    const float* __restrict__ off_b,
                    const float* __restrict__ mod_w,
                    const float* __restrict__ mod_b)
{
    __shared__ __align__(16) float sw[16 * 576];
    __shared__ __align__(16) float sp[2][4 * SPA];
    __shared__ float sb[16];

    const int tx = threadIdx.x, ty = threadIdx.y;
    const int tid = ty * 16 + tx;
    const int bz = blockIdx.z;
    const int b = bz >> 1, half = bz & 1;
    const int base = half * 16;
    const int count = half ? 11 : 16;
    const int bx = blockIdx.x * LTW, by = blockIdx.y * LTH;
    const int x0 = bx + tx * 4, y = by + ty;

    for (int i = tid; i < 16 * 576; i += 256) {
        int lo = i / 576, rest = i - lo * 576;
        int oc = base + lo;
        float v = 0.f;
        if (oc < 18) v = off_w[(size_t)oc * 576 + rest];
        else if (oc < 27) v = mod_w[(size_t)(oc - 18) * 576 + rest];
        sw[rest * 16 + lo] = v;
    }
    if (tid < 16) {
        int oc = base + tid;
        sb[tid] = (oc < 18) ? off_b[oc] : (oc < 27 ? mod_b[oc - 18] : 0.f);
    }

    const float* xb = g_hs + (size_t)b * CIN_D * HW;

    #pragma unroll
    for (int cc = 0; cc < 4; cc++)
        stage_patch16(sp[0] + cc * SPA, xb + (size_t)cc * HW, bx, by, tid);
    CP_COMMIT();

    __syncthreads();

    ull acc2[8][4];
    #pragma unroll
    for (int q = 0; q < 8; q++) {
        ull bv = pack2(sb[2*q], sb[2*q+1]);
        #pragma unroll
        for (int px = 0; px < 4; px++) acc2[q][px] = bv;
    }

    for (int cb = 0; cb < 16; cb++) {
        int cur = cb & 1;
        CP_WAIT0();
        __syncthreads();
        if (cb + 1 < 16) {
            int cn = (cb + 1) * 4;
            #pragma unroll
            for (int cc = 0; cc < 4; cc++)
                stage_patch16(sp[cur ^ 1] + cc * SPA, xb + (size_t)(cn + cc) * HW, bx, by, tid);
        }
        CP_COMMIT();
        int c0 = cb * 4;
        #pragma unroll
        for (int cc = 0; cc < 4; cc++)
            conv_accum_p<8>(acc2, sp[cur] + cc * SPA, sw + (c0 + cc) * 144, tx, ty);
    }

    if (y < Hh) {
        const int p = y * Ww + x0;
        #pragma unroll
        for (int lo = 0; lo < 16; lo++) {
            if (lo >= count) break;
            int oc = base + lo;
            float o4[4];
            #pragma unroll
            for (int px = 0; px < 4; px++) {
                float2 u = unpack2(acc2[lo >> 1][px]);
                o4[px] = (lo & 1) ? u.y : u.x;
            }
            if (oc >= 18) {
                #pragma unroll
                for (int px = 0; px < 4; px++) o4[px] = 2.f * sig_(o4[px]);
            }
            *(float4*)(g_om + ((size_t)b * 27 + oc) * HW + p) = *(float4*)o4;
        }
    }
}

// ---------------------------------------------------------------------------
// Modulated deformable conv. (R8 best version — scattered global gather)
// ---------------------------------------------------------------------------
__global__ __launch_bounds__(256)
void deform_kernel(const float* __restrict__ def_w,
                   const float* __restrict__ def_b)
{
    __shared__ __align__(16) float swd[NK * CIN_D * 9];
    __shared__ float sb[NK];

    const int bx = blockIdx.x * 32, by = blockIdx.y * 8;
    const int b = blockIdx.z;
    const int tx = threadIdx.x, ty = threadIdx.y;
    const int tid = ty * 32 + tx;

    for (int i = tid; i < NK * CIN_D * 9; i += 256) {
        int o = i / 576, rest = i - o * 576;
        swd[rest * 16 + o] = def_w[i];
    }
    if (tid < NK) sb[tid] = def_b[tid];
    __syncthreads();

    const int x = bx + tx, y = by + ty;
    if (y >= Hh) return;
    const int p = y * Ww + x;

    const float* xb = g_hs + (size_t)b * CIN_D * HW;
    const float* om = g_om + (size_t)b * 27 * HW;

    ull acc2[8];
    #pragma unroll
    for (int q = 0; q < 8; q++) acc2[q] = pack2(sb[2*q], sb[2*q+1]);

    #pragma unroll
    for (int j = 0; j < 9; j++) {
        int ky = j / 3, kx = j - ky * 3;
        float dy = om[(2 * j) * HW + p];
        float dx = om[(2 * j + 1) * HW + p];
        float m  = om[(18 + j) * HW + p];
        float py = (float)(y - 1 + ky) + dy;
        float px_ = (float)(x - 1 + kx) + dx;
        float y0f = floorf(py), x0f = floorf(px_);
        float wy = py - y0f, wx = px_ - x0f;
        int y0 = (int)y0f, x0 = (int)x0f;
        int y1 = y0 + 1,   x1 = x0 + 1;
        float vy0 = (y0 >= 0 && y0 < Hh) ? 1.f : 0.f;
        float vy1 = (y1 >= 0 && y1 < Hh) ? 1.f : 0.f;
        float vx0 = (x0 >= 0 && x0 < Ww) ? 1.f : 0.f;
        float vx1 = (x1 >= 0 && x1 < Ww) ? 1.f : 0.f;
        int y0c = min(max(y0, 0), Hh - 1), y1c = min(max(y1, 0), Hh - 1);
        int x0c = min(max(x0, 0), Ww - 1), x1c = min(max(x1, 0), Ww - 1);
        float w00 = (1.f - wy) * (1.f - wx) * vy0 * vx0 * m;
        float w01 = (1.f - wy) * wx         * vy0 * vx1 * m;
        float w10 = wy * (1.f - wx)         * vy1 * vx0 * m;
        float w11 = wy * wx                 * vy1 * vx1 * m;
        int o00 = y0c * Ww + x0c, o01 = y0c * Ww + x1c;
        int o10 = y1c * Ww + x0c, o11 = y1c * Ww + x1c;

        #pragma unroll 4
        for (int c = 0; c < CIN_D; c++) {
            const float* pc_ = xb + (size_t)c * HW;
            float s = w00 * pc_[o00] + w01 * pc_[o01]
                    + w10 * pc_[o10] + w11 * pc_[o11];
            ull ss = pack2(s, s);
            const ulonglong2* w2 = (const ulonglong2*)(swd + (c * 9 + j) * 16);
            ulonglong2 wa = w2[0], wb = w2[1], wc2 = w2[2], wd = w2[3];
            ffma2(acc2[0], ss, wa.x); ffma2(acc2[1], ss, wa.y);
            ffma2(acc2[2], ss, wb.x); ffma2(acc2[3], ss, wb.y);
            ffma2(acc2[4], ss, wc2.x); ffma2(acc2[5], ss, wc2.y);
            ffma2(acc2[6], ss, wd.x); ffma2(acc2[7], ss, wd.y);
        }
    }

    #pragma unroll
    for (int q = 0; q < 8; q++) {
        float2 u = unpack2(acc2[q]);
        g_def[((size_t)b * NK + 2*q    ) * HW + p] = u.x;
        g_def[((size_t)b * NK + 2*q + 1) * HW + p] = u.y;
    }
}

// ---------------------------------------------------------------------------
// Output conv 16 -> 48 (3 groups of 16) + pixel shuffle + clip. (R8 version)
// ---------------------------------------------------------------------------
__global__ __launch_bounds__(256, 2)
void outconv_kernel(const float* __restrict__ out_w,
                    const float* __restrict__ out_b,
                    float* __restrict__ out)
{
    __shared__ __align__(16) float sw[16 * 144];
    __shared__ __align__(16) float sp[2][4 * SPA];
    __shared__ float sb[16];

    const int tx = threadIdx.x, ty = threadIdx.y;
    const int tid = ty * 16 + tx;
    const int bz = blockIdx.z;
    const int b = bz / 3, g3 = bz - b * 3;
    const int base = g3 * 16;
    const int bx = blockIdx.x * LTW, by = blockIdx.y * LTH;
    const int x0 = bx + tx * 4, y = by + ty;

    for (int i = tid; i < 16 * 144; i += 256) {
        int lo = i / 144, rest = i - lo * 144;
        sw[rest * 16 + lo] = out_w[(size_t)(base + lo) * 144 + rest];
    }
    if (tid < 16) sb[tid] = out_b[base + tid];

    const float* xb = g_def + (size_t)b * NK * HW;

    #pragma unroll
    for (int cc = 0; cc < 4; cc++)
        stage_patch16(sp[0] + cc * SPA, xb + (size_t)cc * HW, bx, by, tid);
    CP_COMMIT();

    __syncthreads();

    ull acc2[8][4];
    #pragma unroll
    for (int q = 0; q < 8; q++) {
        ull bv = pack2(sb[2*q], sb[2*q+1]);
        #pragma unroll
        for (int px = 0; px < 4; px++) acc2[q][px] = bv;
    }

    for (int cb = 0; cb < 4; cb++) {
        int cur = cb & 1;
        CP_WAIT0();
        __syncthreads();
        if (cb + 1 < 4) {
            int cn = (cb + 1) * 4;
            #pragma unroll
            for (int cc = 0; cc < 4; cc++)
                stage_patch16(sp[cur ^ 1] + cc * SPA, xb + (size_t)(cn + cc) * HW, bx, by, tid);
        }
        CP_COMMIT();
        int c0 = cb * 4;
        #pragma unroll
        for (int cc = 0; cc < 4; cc++)
            conv_accum_p<8>(acc2, sp[cur] + cc * SPA, sw + (c0 + cc) * 144, tx, ty);
    }

    if (y < Hh) {
        #pragma unroll
        for (int lo = 0; lo < 16; lo++) {
            int oc = base + lo;
            int cch = oc >> 4, rem = oc & 15;
            int r1 = rem >> 2, r2 = rem & 3;
            #pragma unroll
            for (int px = 0; px < 4; px++) {
                float2 u = unpack2(acc2[lo >> 1][px]);
                float val = (lo & 1) ? u.y : u.x;
                val = fminf(fmaxf(val, 0.f), 255.f);
                size_t oi = (((size_t)b * NC + cch) * (Hh * SCALE) + (y * SCALE + r1))
                            * (size_t)(Ww * SCALE) + ((x0 + px) * SCALE + r2);
                out[oi] = val;
            }
        }
    }
}

// ---------------------------------------------------------------------------
extern "C" void kernel_launch(void* const* d_in, const int* in_sizes, int n_in,
                              void* d_out, int out_size)
{
    const float* X      = (const float*)d_in[0];
    const float* lstm_w = (const float*)d_in[1];
    const float* lstm_b = (const float*)d_in[2];
    const float* W_ci   = (const float*)d_in[3];
    const float* W_cf   = (const float*)d_in[4];
    const float* W_co   = (const float*)d_in[5];
    const float* off_w  = (const float*)d_in[6];
    const float* off_b  = (const float*)d_in[7];
    const float* mod_w  = (const float*)d_in[8];
    const float* mod_b  = (const float*)d_in[9];
    const float* def_w  = (const float*)d_in[10];
    const float* def_b  = (const float*)d_in[11];
    const float* out_w  = (const float*)d_in[12];
    const float* out_b  = (const float*)d_in[13];
    float* out = (float*)d_out;

    dim3 blk32x8(32, 8);
    dim3 grid_lstm(Ww / LTW, (Hh + LTH2 - 1) / LTH2, Bn * 4);   // 5 x 23 x 8

    dim3 blk16(16, 16);
    dim3 grid_om(Ww / LTW, (Hh + LTH - 1) / LTH, Bn * 2);
    dim3 grid_oc(Ww / LTW, (Hh + LTH - 1) / LTH, Bn * 3);

    for (int t = 0; t < Tt; t++)
        lstm_step_kernel<<<grid_lstm, blk32x8>>>(X, lstm_w, lstm_b, W_ci, W_cf, W_co, t);

    offmask_kernel<<<grid_om, blk16>>>(off_w, off_b, mod_w, mod_b);

    dim3 grid_def(Ww / 32, (Hh + 7) / 8, Bn);
    deform_kernel<<<grid_def, blk32x8>>>(def_w, def_b);

    outconv_kernel<<<grid_oc, blk16>>>(out_w, out_b, out);
}

// round 12
// speedup vs baseline: 1.0814x; 1.0165x over previous
#include <cuda_runtime.h>
#include <math.h>

#define Bn 2
#define Tt 4
#define NC 3
#define NK 16
#define Hh 180
#define Ww 320
#define HW (Hh*Ww)
#define CIN_D (Tt*NK)   // 64
#define OUT_C 48
#define SCALE 4

#define LTW 64
#define LTH 16
#define SPW 72
#define SPH 18
#define SPA (SPH*SPW)
#define SPF (SPH*18)

// lstm tile: 64 x 8, 2 px/thread
#define LTH2 8
#define SPH2 10
#define SPA2 (SPH2*SPW)   // 720
#define SPF2 (SPH2*18)    // 180

typedef unsigned long long ull;

// Scratch (no cudaMalloc allowed)
__device__ float g_hs[Bn*CIN_D*HW];
__device__ float g_c[Bn*NK*HW];
__device__ float g_om[Bn*27*HW];
__device__ float g_def[Bn*NK*HW];

__device__ __forceinline__ float sig_(float v) {
    return __fdividef(1.f, 1.f + __expf(-v));
}
__device__ __forceinline__ float tanh_(float v) {
    float e = __expf(2.f * v);
    return 1.f - __fdividef(2.f, e + 1.f);
}

// ---- packed f32x2 helpers ----
__device__ __forceinline__ ull pack2(float lo, float hi) {
    ull r;
    asm("mov.b64 %0, {%1, %2};" : "=l"(r) : "f"(lo), "f"(hi));
    return r;
}
__device__ __forceinline__ void ffma2(ull& d, ull a, ull b) {
    asm("fma.rn.f32x2 %0, %1, %2, %0;" : "+l"(d) : "l"(a), "l"(b));
}
__device__ __forceinline__ float2 unpack2(ull v) {
    float2 f;
    asm("mov.b64 {%0, %1}, %2;" : "=f"(f.x), "=f"(f.y) : "l"(v));
    return f;
}

__device__ __forceinline__ void cp_async16(float* dst_smem, const float* src) {
    unsigned d = (unsigned)__cvta_generic_to_shared(dst_smem);
    asm volatile("cp.async.cg.shared.global [%0], [%1], 16;" :: "r"(d), "l"(src));
}
#define CP_COMMIT() asm volatile("cp.async.commit_group;" ::: "memory")
#define CP_WAIT0()  asm volatile("cp.async.wait_group 0;" ::: "memory")

// stage one conv patch (gx in [bx-4, bx+68)), 18-row version
__device__ __forceinline__ void stage_patch16(float* dst, const float* src,
                                              int bx, int by, int tid)
{
    #pragma unroll
    for (int i = tid; i < SPF; i += 256) {
        int pr = i / 18, f = i - pr * 18;
        int gy = by - 1 + pr;
        int gxf = bx - 4 + f * 4;
        float* d = dst + pr * SPW + f * 4;
        if (gy >= 0 && gy < Hh && gxf >= 0 && gxf + 4 <= Ww)
            cp_async16(d, src + gy * Ww + gxf);
        else
            *(float4*)d = make_float4(0.f, 0.f, 0.f, 0.f);
    }
}

// 10-row version for the lstm tile
__device__ __forceinline__ void stage_patch16_8(float* dst, const float* src,
                                                int bx, int by, int tid)
{
    #pragma unroll
    for (int i = tid; i < SPF2; i += 256) {
        int pr = i / 18, f = i - pr * 18;
        int gy = by - 1 + pr;
        int gxf = bx - 4 + f * 4;
        float* d = dst + pr * SPW + f * 4;
        if (gy >= 0 && gy < Hh && gxf >= 0 && gxf + 4 <= Ww)
            cp_async16(d, src + gy * Ww + gxf);
        else
            *(float4*)d = make_float4(0.f, 0.f, 0.f, 0.f);
    }
}

// one channel's 3x3 conv; acc2[q][px] = outputs (2q,2q+1) at pixel px (4 px).
// weight stride 16 floats/tap.
template<int NQ>
__device__ __forceinline__ void conv_accum_p(ull acc2[][4], const float* patch,
                                             const float* wc, int tx, int ty)
{
    #pragma unroll
    for (int tr = 0; tr < 3; tr++) {
        const float2* rp = (const float2*)(patch + (ty + tr) * SPW + tx * 4 + 2);
        float2 a = rp[0], b = rp[1], c = rp[2], d = rp[3];
        float v[6] = {a.y, b.x, b.y, c.x, c.y, d.x};
        ull vv[6];
        #pragma unroll
        for (int j = 0; j < 6; j++) vv[j] = pack2(v[j], v[j]);
        #pragma unroll
        for (int tc = 0; tc < 3; tc++) {
            const ulonglong2* w2 = (const ulonglong2*)(wc + (tr * 3 + tc) * 16);
            ulonglong2 wa = w2[0], wb = w2[1], wcq = w2[2], wd = w2[3];
            ull wp[8] = {wa.x, wa.y, wb.x, wb.y, wcq.x, wcq.y, wd.x, wd.y};
            #pragma unroll
            for (int q = 0; q < NQ; q++) {
                #pragma unroll
                for (int px = 0; px < 4; px++)
                    ffma2(acc2[q][px], vv[tc + px], wp[q]);
            }
        }
    }
}

// 5-pair (10-output) variant, weight stride 12 floats/tap
__device__ __forceinline__ void conv_accum_o(ull acc2[5][4], const float* patch,
                                             const float* wc, int tx, int ty)
{
    #pragma unroll
    for (int tr = 0; tr < 3; tr++) {
        const float2* rp = (const float2*)(patch + (ty + tr) * SPW + tx * 4 + 2);
        float2 a = rp[0], b = rp[1], c = rp[2], d = rp[3];
        float v[6] = {a.y, b.x, b.y, c.x, c.y, d.x};
        ull vv[6];
        #pragma unroll
        for (int j = 0; j < 6; j++) vv[j] = pack2(v[j], v[j]);
        #pragma unroll
        for (int tc = 0; tc < 3; tc++) {
            const float* wt = wc + (tr * 3 + tc) * 12;
            ulonglong2 wa = *(const ulonglong2*)wt;
            ulonglong2 wb = *(const ulonglong2*)(wt + 4);
            ull wp4 = *(const ull*)(wt + 8);
            ull wp[5] = {wa.x, wa.y, wb.x, wb.y, wp4};
            #pragma unroll
            for (int q = 0; q < 5; q++) {
                #pragma unroll
                for (int px = 0; px < 4; px++)
                    ffma2(acc2[q][px], vv[tc + px], wp[q]);
            }
        }
    }
}

// 2-px variant for the lstm kernel (tx in [0,32))
__device__ __forceinline__ void conv_accum_p2(ull acc2[8][2], const float* patch,
                                              const float* wc, int tx, int ty)
{
    #pragma unroll
    for (int tr = 0; tr < 3; tr++) {
        const float2* rp = (const float2*)(patch + (ty + tr) * SPW + tx * 2 + 2);
        float2 a = rp[0], b = rp[1], c = rp[2];
        float v[4] = {a.y, b.x, b.y, c.x};
        ull vv[4];
        #pragma unroll
        for (int j = 0; j < 4; j++) vv[j] = pack2(v[j], v[j]);
        #pragma unroll
        for (int tc = 0; tc < 3; tc++) {
            const ulonglong2* w2 = (const ulonglong2*)(wc + (tr * 3 + tc) * 16);
            ulonglong2 wa = w2[0], wb = w2[1], wcq = w2[2], wd = w2[3];
            ull wp[8] = {wa.x, wa.y, wb.x, wb.y, wcq.x, wcq.y, wd.x, wd.y};
            #pragma unroll
            for (int q = 0; q < 8; q++) {
                #pragma unroll
                for (int px = 0; px < 2; px++)
                    ffma2(acc2[q][px], vv[tc + px], wp[q]);
            }
        }
    }
}

// ---------------------------------------------------------------------------
// ConvLSTM step. block (32,8); thread = 2 px, 16 outputs. (R11 winner)
// ---------------------------------------------------------------------------
__global__ __launch_bounds__(256, 3)
void lstm_step_kernel(const float* __restrict__ X,
                      const float* __restrict__ lw,
                      const float* __restrict__ lb,
                      const float* __restrict__ Wci,
                      const float* __restrict__ Wcf,
                      const float* __restrict__ Wco,
                      int t)
{
    __shared__ __align__(16) float sw[19 * 9 * 16];
    __shared__ __align__(16) float sp[2][4 * SPA2];
    __shared__ float sb[16];

    const int tx = threadIdx.x, ty = threadIdx.y;
    const int tid = ty * 32 + tx;
    const int bz = blockIdx.z;
    const int b = bz >> 2, kg = bz & 3;
    const int bx = blockIdx.x * LTW, by = blockIdx.y * LTH2;
    const int x0 = bx + tx * 2, y = by + ty;

    for (int i = tid; i < 19 * 144; i += 256) {
        int lo = i / 171, rest = i - lo * 171;
        int row = (lo >> 2) * NK + kg * 4 + (lo & 3);
        sw[rest * 16 + lo] = lw[row * 171 + rest];
    }
    if (tid < 16)
        sb[tid] = lb[(tid >> 2) * NK + kg * 4 + (tid & 3)];

    const int ncin = (t == 0) ? NC : (NC + NK);
    const int nb = (ncin + 3) >> 2;

    #define LSTM_SRC(c) ((c) < NC \
        ? (X + (((size_t)b * Tt + t) * NC + (c)) * HW) \
        : (g_hs + ((size_t)b * CIN_D + (t - 1) * NK + ((c) - NC)) * HW))

    #pragma unroll
    for (int cc = 0; cc < 4; cc++)
        if (cc < ncin) stage_patch16_8(sp[0] + cc * SPA2, LSTM_SRC(cc), bx, by, tid);
    CP_COMMIT();

    __syncthreads();   // sb/sw visible

    ull acc2[8][2];
    #pragma unroll
    for (int q = 0; q < 8; q++) {
        ull bv = pack2(sb[2*q], sb[2*q+1]);
        acc2[q][0] = bv; acc2[q][1] = bv;
    }

    for (int cb = 0; cb < nb; cb++) {
        int cur = cb & 1;
        CP_WAIT0();
        __syncthreads();
        if (cb + 1 < nb) {
            int cn = (cb + 1) * 4;
            #pragma unroll
            for (int cc = 0; cc < 4; cc++)
                if (cn + cc < ncin)
                    stage_patch16_8(sp[cur ^ 1] + cc * SPA2, LSTM_SRC(cn + cc), bx, by, tid);
        }
        CP_COMMIT();
        int c0 = cb * 4;
        #pragma unroll
        for (int cc = 0; cc < 4; cc++)
            if (c0 + cc < ncin)
                conv_accum_p2(acc2, sp[cur] + cc * SPA2, sw + (c0 + cc) * 144, tx, ty);
    }
    #undef LSTM_SRC

    if (y < Hh) {
        const int p = y * Ww + x0;
        float accf[16][2];
        #pragma unroll
        for (int q = 0; q < 8; q++) {
            float2 u0 = unpack2(acc2[q][0]);
            float2 u1 = unpack2(acc2[q][1]);
            accf[2*q][0] = u0.x;   accf[2*q][1] = u1.x;
            accf[2*q+1][0] = u0.y; accf[2*q+1][1] = u1.y;
        }
        #pragma unroll
        for (int kk = 0; kk < 4; kk++) {
            int k = kg * 4 + kk;
            float2 ci2 = *(const float2*)(Wci + k * HW + p);
            float2 cf2 = *(const float2*)(Wcf + k * HW + p);
            float2 co2 = *(const float2*)(Wco + k * HW + p);
            float2 cp2 = make_float2(0.f, 0.f);
            if (t != 0)
                cp2 = *(const float2*)(g_c + ((size_t)b * NK + k) * HW + p);
            float ci_[2] = {ci2.x, ci2.y}, cf_[2] = {cf2.x, cf2.y};
            float co_[2] = {co2.x, co2.y}, cp_[2] = {cp2.x, cp2.y};
            float cn_[2], h_[2];
            #pragma unroll
            for (int px = 0; px < 2; px++) {
                float cprev = cp_[px];
                float i_ = sig_(accf[kk][px]      + ci_[px] * cprev);
                float f_ = sig_(accf[4 + kk][px]  + cf_[px] * cprev);
                float cn = f_ * cprev + i_ * tanh_(accf[8 + kk][px]);
                float o_ = sig_(accf[12 + kk][px] + co_[px] * cn);
                cn_[px] = cn;
                h_[px] = o_ * tanh_(cn);
            }
            *(float2*)(g_c + ((size_t)b * NK + k) * HW + p) = make_float2(cn_[0], cn_[1]);
            *(float2*)(g_hs + ((size_t)b * CIN_D + t * NK + k) * HW + p) = make_float2(h_[0], h_[1]);
        }
    }
}

// ---------------------------------------------------------------------------
// Offset+mask conv 64 -> 27. 3 groups of 10 computed / 9 stored (base = g*9).
// 4 px/thread, acc2[5][4], 3 CTAs/SM. blockIdx.z = b*3 + g.
// ---------------------------------------------------------------------------
__global__ __launch_bounds__(256, 3)
void offmask_kernel(const float* __restrict__ off_w,
                    const float* __restrict__ off_b,
                    const float* __restrict__ mod_w,
                    const float* __restrict__ mod_b)
{
    __shared__ __align__(16) float sw[12 * 576];   // [tap][12] stride-12
    __shared__ __align__(16) float sp[2][4 * SPA];
    __shared__ float sb[12];

    const int tx = threadIdx.x, ty = threadIdx.y;
    const int tid = ty * 16 + tx;
    const int bz = blockIdx.z;
    const int b = bz / 3, g = bz - b * 3;
    const int base = g * 9;
    const int bx = blockIdx.x * LTW, by = blockIdx.y * LTH;
    const int x0 = bx + tx * 4, y = by + ty;

    for (int i = tid; i < 12 * 576; i += 256) {
        int rest = i / 12, lo = i - rest * 12;
        int oc = base + lo;
        float v = 0.f;
        if (lo < 10 && oc < 27) {
            if (oc < 18) v = off_w[(size_t)oc * 576 + rest];
            else v = mod_w[(size_t)(oc - 18) * 576 + rest];
        }
        sw[rest * 12 + lo] = v;
    }
    if (tid < 12) {
        int oc = base + tid;
        float v = 0.f;
        if (tid < 10 && oc < 27) v = (oc < 18) ? off_b[oc] : mod_b[oc - 18];
        sb[tid] = v;
    }

    const float* xb = g_hs + (size_t)b * CIN_D * HW;

    #pragma unroll
    for (int cc = 0; cc < 4; cc++)
        stage_patch16(sp[0] + cc * SPA, xb + (size_t)cc * HW, bx, by, tid);
    CP_COMMIT();

    __syncthreads();

    ull acc2[5][4];
    #pragma unroll
    for (int q = 0; q < 5; q++) {
        ull bv = pack2(sb[2*q], sb[2*q+1]);
        #pragma unroll
        for (int px = 0; px < 4; px++) acc2[q][px] = bv;
    }

    for (int cb = 0; cb < 16; cb++) {
        int cur = cb & 1;
        CP_WAIT0();
        __syncthreads();
        if (cb + 1 < 16) {
            int cn = (cb + 1) * 4;
            #pragma unroll
            for (int cc = 0; cc < 4; cc++)
                stage_patch16(sp[cur ^ 1] + cc * SPA, xb + (size_t)(cn + cc) * HW, bx, by, tid);
        }
        CP_COMMIT();
        int c0 = cb * 4;
        #pragma unroll
        for (int cc = 0; cc < 4; cc++)
            conv_accum_o(acc2, sp[cur] + cc * SPA, sw + (c0 + cc) * 108, tx, ty);
    }

    if (y < Hh) {
        const int p = y * Ww + x0;
        #pragma unroll
        for (int lo = 0; lo < 9; lo++) {
            int oc = base + lo;
            float o4[4];
            #pragma unroll
            for (int px = 0; px < 4; px++) {
                float2 u = unpack2(acc2[lo >> 1][px]);
                o4[px] = (lo & 1) ? u.y : u.x;
            }
            if (oc >= 18) {
                #pragma unroll
                for (int px = 0; px < 4; px++) o4[px] = 2.f * sig_(o4[px]);
            }
            *(float4*)(g_om + ((size_t)b * 27 + oc) * HW + p) = *(float4*)o4;
        }
    }
}

// ---------------------------------------------------------------------------
// Modulated deformable conv. (R8/R11 best version)
// ---------------------------------------------------------------------------
__global__ __launch_bounds__(256)
void deform_kernel(const float* __restrict__ def_w,
                   const float* __restrict__ def_b)
{
    __shared__ __align__(16) float swd[NK * CIN_D * 9];
    __shared__ float sb[NK];

    const int bx = blockIdx.x * 32, by = blockIdx.y * 8;
    const int b = blockIdx.z;
    const int tx = threadIdx.x, ty = threadIdx.y;
    const int tid = ty * 32 + tx;

    for (int i = tid; i < NK * CIN_D * 9; i += 256) {
        int o = i / 576, rest = i - o * 576;
        swd[rest * 16 + o] = def_w[i];
    }
    if (tid < NK) sb[tid] = def_b[tid];
    __syncthreads();

    const int x = bx + tx, y = by + ty;
    if (y >= Hh) return;
    const int p = y * Ww + x;

    const float* xb = g_hs + (size_t)b * CIN_D * HW;
    const float* om = g_om + (size_t)b * 27 * HW;

    ull acc2[8];
    #pragma unroll
    for (int q = 0; q < 8; q++) acc2[q] = pack2(sb[2*q], sb[2*q+1]);

    #pragma unroll
    for (int j = 0; j < 9; j++) {
        int ky = j / 3, kx = j - ky * 3;
        float dy = om[(2 * j) * HW + p];
        float dx = om[(2 * j + 1) * HW + p];
        float m  = om[(18 + j) * HW + p];
        float py = (float)(y - 1 + ky) + dy;
        float px_ = (float)(x - 1 + kx) + dx;
        float y0f = floorf(py), x0f = floorf(px_);
        float wy = py - y0f, wx = px_ - x0f;
        int y0 = (int)y0f, x0 = (int)x0f;
        int y1 = y0 + 1,   x1 = x0 + 1;
        float vy0 = (y0 >= 0 && y0 < Hh) ? 1.f : 0.f;
        float vy1 = (y1 >= 0 && y1 < Hh) ? 1.f : 0.f;
        float vx0 = (x0 >= 0 && x0 < Ww) ? 1.f : 0.f;
        float vx1 = (x1 >= 0 && x1 < Ww) ? 1.f : 0.f;
        int y0c = min(max(y0, 0), Hh - 1), y1c = min(max(y1, 0), Hh - 1);
        int x0c = min(max(x0, 0), Ww - 1), x1c = min(max(x1, 0), Ww - 1);
        float w00 = (1.f - wy) * (1.f - wx) * vy0 * vx0 * m;
        float w01 = (1.f - wy) * wx         * vy0 * vx1 * m;
        float w10 = wy * (1.f - wx)         * vy1 * vx0 * m;
        float w11 = wy * wx                 * vy1 * vx1 * m;
        int o00 = y0c * Ww + x0c, o01 = y0c * Ww + x1c;
        int o10 = y1c * Ww + x0c, o11 = y1c * Ww + x1c;

        #pragma unroll 4
        for (int c = 0; c < CIN_D; c++) {
            const float* pc_ = xb + (size_t)c * HW;
            float s = w00 * pc_[o00] + w01 * pc_[o01]
                    + w10 * pc_[o10] + w11 * pc_[o11];
            ull ss = pack2(s, s);
            const ulonglong2* w2 = (const ulonglong2*)(swd + (c * 9 + j) * 16);
            ulonglong2 wa = w2[0], wb = w2[1], wc2 = w2[2], wd = w2[3];
            ffma2(acc2[0], ss, wa.x); ffma2(acc2[1], ss, wa.y);
            ffma2(acc2[2], ss, wb.x); ffma2(acc2[3], ss, wb.y);
            ffma2(acc2[4], ss, wc2.x); ffma2(acc2[5], ss, wc2.y);
            ffma2(acc2[6], ss, wd.x); ffma2(acc2[7], ss, wd.y);
        }
    }

    #pragma unroll
    for (int q = 0; q < 8; q++) {
        float2 u = unpack2(acc2[q]);
        g_def[((size_t)b * NK + 2*q    ) * HW + p] = u.x;
        g_def[((size_t)b * NK + 2*q + 1) * HW + p] = u.y;
    }
}

// ---------------------------------------------------------------------------
// Output conv 16 -> 48 (3 groups of 16) + pixel shuffle + clip. (R8 version)
// ---------------------------------------------------------------------------
__global__ __launch_bounds__(256, 2)
void outconv_kernel(const float* __restrict__ out_w,
                    const float* __restrict__ out_b,
                    float* __restrict__ out)
{
    __shared__ __align__(16) float sw[16 * 144];
    __shared__ __align__(16) float sp[2][4 * SPA];
    __shared__ float sb[16];

    const int tx = threadIdx.x, ty = threadIdx.y;
    const int tid = ty * 16 + tx;
    const int bz = blockIdx.z;
    const int b = bz / 3, g3 = bz - b * 3;
    const int base = g3 * 16;
    const int bx = blockIdx.x * LTW, by = blockIdx.y * LTH;
    const int x0 = bx + tx * 4, y = by + ty;

    for (int i = tid; i < 16 * 144; i += 256) {
        int lo = i / 144, rest = i - lo * 144;
        sw[rest * 16 + lo] = out_w[(size_t)(base + lo) * 144 + rest];
    }
    if (tid < 16) sb[tid] = out_b[base + tid];

    const float* xb = g_def + (size_t)b * NK * HW;

    #pragma unroll
    for (int cc = 0; cc < 4; cc++)
        stage_patch16(sp[0] + cc * SPA, xb + (size_t)cc * HW, bx, by, tid);
    CP_COMMIT();

    __syncthreads();

    ull acc2[8][4];
    #pragma unroll
    for (int q = 0; q < 8; q++) {
        ull bv = pack2(sb[2*q], sb[2*q+1]);
        #pragma unroll
        for (int px = 0; px < 4; px++) acc2[q][px] = bv;
    }

    for (int cb = 0; cb < 4; cb++) {
        int cur = cb & 1;
        CP_WAIT0();
        __syncthreads();
        if (cb + 1 < 4) {
            int cn = (cb + 1) * 4;
            #pragma unroll
            for (int cc = 0; cc < 4; cc++)
                stage_patch16(sp[cur ^ 1] + cc * SPA, xb + (size_t)(cn + cc) * HW, bx, by, tid);
        }
        CP_COMMIT();
        int c0 = cb * 4;
        #pragma unroll
        for (int cc = 0; cc < 4; cc++)
            conv_accum_p<8>(acc2, sp[cur] + cc * SPA, sw + (c0 + cc) * 144, tx, ty);
    }

    if (y < Hh) {
        #pragma unroll
        for (int lo = 0; lo < 16; lo++) {
            int oc = base + lo;
            int cch = oc >> 4, rem = oc & 15;
            int r1 = rem >> 2, r2 = rem & 3;
            #pragma unroll
            for (int px = 0; px < 4; px++) {
                float2 u = unpack2(acc2[lo >> 1][px]);
                float val = (lo & 1) ? u.y : u.x;
                val = fminf(fmaxf(val, 0.f), 255.f);
                size_t oi = (((size_t)b * NC + cch) * (Hh * SCALE) + (y * SCALE + r1))
                            * (size_t)(Ww * SCALE) + ((x0 + px) * SCALE + r2);
                out[oi] = val;
            }
        }
    }
}

// ---------------------------------------------------------------------------
extern "C" void kernel_launch(void* const* d_in, const int* in_sizes, int n_in,
                              void* d_out, int out_size)
{
    const float* X      = (const float*)d_in[0];
    const float* lstm_w = (const float*)d_in[1];
    const float* lstm_b = (const float*)d_in[2];
    const float* W_ci   = (const float*)d_in[3];
    const float* W_cf   = (const float*)d_in[4];
    const float* W_co   = (const float*)d_in[5];
    const float* off_w  = (const float*)d_in[6];
    const float* off_b  = (const float*)d_in[7];
    const float* mod_w  = (const float*)d_in[8];
    const float* mod_b  = (const float*)d_in[9];
    const float* def_w  = (const float*)d_in[10];
    const float* def_b  = (const float*)d_in[11];
    const float* out_w  = (const float*)d_in[12];
    const float* out_b  = (const float*)d_in[13];
    float* out = (float*)d_out;

    dim3 blk32x8(32, 8);
    dim3 grid_lstm(Ww / LTW, (Hh + LTH2 - 1) / LTH2, Bn * 4);

    dim3 blk16(16, 16);
    dim3 grid_om(Ww / LTW, (Hh + LTH - 1) / LTH, Bn * 3);   // 3 output groups
    dim3 grid_oc(Ww / LTW, (Hh + LTH - 1) / LTH, Bn * 3);

    for (int t = 0; t < Tt; t++)
        lstm_step_kernel<<<grid_lstm, blk32x8>>>(X, lstm_w, lstm_b, W_ci, W_cf, W_co, t);

    offmask_kernel<<<grid_om, blk16>>>(off_w, off_b, mod_w, mod_b);

    dim3 grid_def(Ww / 32, (Hh + 7) / 8, Bn);
    deform_kernel<<<grid_def, blk32x8>>>(def_w, def_b);

    outconv_kernel<<<grid_oc, blk16>>>(out_w, out_b, out);
}

// round 13
// speedup vs baseline: 1.1113x; 1.0276x over previous
#include <cuda_runtime.h>
#include <math.h>

#define Bn 2
#define Tt 4
#define NC 3
#define NK 16
#define Hh 180
#define Ww 320
#define HW (Hh*Ww)
#define CIN_D (Tt*NK)   // 64
#define OUT_C 48
#define SCALE 4

#define LTW 64
#define LTH 16
#define SPW 72
#define SPH 18
#define SPA (SPH*SPW)
#define SPF (SPH*18)

// 8-row tiles (2 px/thread kernels)
#define LTH2 8
#define SPH2 10
#define SPA2 (SPH2*SPW)   // 720
#define SPF2 (SPH2*18)    // 180

typedef unsigned long long ull;

// Scratch (no cudaMalloc allowed)
__device__ float g_hs[Bn*CIN_D*HW];
__device__ float g_c[Bn*NK*HW];
__device__ float g_om[Bn*27*HW];
__device__ float g_def[Bn*NK*HW];

__device__ __forceinline__ float sig_(float v) {
    return __fdividef(1.f, 1.f + __expf(-v));
}
__device__ __forceinline__ float tanh_(float v) {
    float e = __expf(2.f * v);
    return 1.f - __fdividef(2.f, e + 1.f);
}

// ---- packed f32x2 helpers ----
__device__ __forceinline__ ull pack2(float lo, float hi) {
    ull r;
    asm("mov.b64 %0, {%1, %2};" : "=l"(r) : "f"(lo), "f"(hi));
    return r;
}
__device__ __forceinline__ void ffma2(ull& d, ull a, ull b) {
    asm("fma.rn.f32x2 %0, %1, %2, %0;" : "+l"(d) : "l"(a), "l"(b));
}
__device__ __forceinline__ float2 unpack2(ull v) {
    float2 f;
    asm("mov.b64 {%0, %1}, %2;" : "=f"(f.x), "=f"(f.y) : "l"(v));
    return f;
}

__device__ __forceinline__ void cp_async16(float* dst_smem, const float* src) {
    unsigned d = (unsigned)__cvta_generic_to_shared(dst_smem);
    asm volatile("cp.async.cg.shared.global [%0], [%1], 16;" :: "r"(d), "l"(src));
}
#define CP_COMMIT() asm volatile("cp.async.commit_group;" ::: "memory")
#define CP_WAIT0()  asm volatile("cp.async.wait_group 0;" ::: "memory")

// stage one conv patch (gx in [bx-4, bx+68)), 18-row version
__device__ __forceinline__ void stage_patch16(float* dst, const float* src,
                                              int bx, int by, int tid)
{
    #pragma unroll
    for (int i = tid; i < SPF; i += 256) {
        int pr = i / 18, f = i - pr * 18;
        int gy = by - 1 + pr;
        int gxf = bx - 4 + f * 4;
        float* d = dst + pr * SPW + f * 4;
        if (gy >= 0 && gy < Hh && gxf >= 0 && gxf + 4 <= Ww)
            cp_async16(d, src + gy * Ww + gxf);
        else
            *(float4*)d = make_float4(0.f, 0.f, 0.f, 0.f);
    }
}

// 10-row version for 8-row tiles
__device__ __forceinline__ void stage_patch16_8(float* dst, const float* src,
                                                int bx, int by, int tid)
{
    #pragma unroll
    for (int i = tid; i < SPF2; i += 256) {
        int pr = i / 18, f = i - pr * 18;
        int gy = by - 1 + pr;
        int gxf = bx - 4 + f * 4;
        float* d = dst + pr * SPW + f * 4;
        if (gy >= 0 && gy < Hh && gxf >= 0 && gxf + 4 <= Ww)
            cp_async16(d, src + gy * Ww + gxf);
        else
            *(float4*)d = make_float4(0.f, 0.f, 0.f, 0.f);
    }
}

// 5-pair (10-output) variant, weight stride 12 floats/tap (offmask)
__device__ __forceinline__ void conv_accum_o(ull acc2[5][4], const float* patch,
                                             const float* wc, int tx, int ty)
{
    #pragma unroll
    for (int tr = 0; tr < 3; tr++) {
        const float2* rp = (const float2*)(patch + (ty + tr) * SPW + tx * 4 + 2);
        float2 a = rp[0], b = rp[1], c = rp[2], d = rp[3];
        float v[6] = {a.y, b.x, b.y, c.x, c.y, d.x};
        ull vv[6];
        #pragma unroll
        for (int j = 0; j < 6; j++) vv[j] = pack2(v[j], v[j]);
        #pragma unroll
        for (int tc = 0; tc < 3; tc++) {
            const float* wt = wc + (tr * 3 + tc) * 12;
            ulonglong2 wa = *(const ulonglong2*)wt;
            ulonglong2 wb = *(const ulonglong2*)(wt + 4);
            ull wp4 = *(const ull*)(wt + 8);
            ull wp[5] = {wa.x, wa.y, wb.x, wb.y, wp4};
            #pragma unroll
            for (int q = 0; q < 5; q++) {
                #pragma unroll
                for (int px = 0; px < 4; px++)
                    ffma2(acc2[q][px], vv[tc + px], wp[q]);
            }
        }
    }
}

// 2-px variant (tx in [0,32)), weight stride 16 floats/tap
__device__ __forceinline__ void conv_accum_p2(ull acc2[8][2], const float* patch,
                                              const float* wc, int tx, int ty)
{
    #pragma unroll
    for (int tr = 0; tr < 3; tr++) {
        const float2* rp = (const float2*)(patch + (ty + tr) * SPW + tx * 2 + 2);
        float2 a = rp[0], b = rp[1], c = rp[2];
        float v[4] = {a.y, b.x, b.y, c.x};
        ull vv[4];
        #pragma unroll
        for (int j = 0; j < 4; j++) vv[j] = pack2(v[j], v[j]);
        #pragma unroll
        for (int tc = 0; tc < 3; tc++) {
            const ulonglong2* w2 = (const ulonglong2*)(wc + (tr * 3 + tc) * 16);
            ulonglong2 wa = w2[0], wb = w2[1], wcq = w2[2], wd = w2[3];
            ull wp[8] = {wa.x, wa.y, wb.x, wb.y, wcq.x, wcq.y, wd.x, wd.y};
            #pragma unroll
            for (int q = 0; q < 8; q++) {
                #pragma unroll
                for (int px = 0; px < 2; px++)
                    ffma2(acc2[q][px], vv[tc + px], wp[q]);
            }
        }
    }
}

// ---------------------------------------------------------------------------
// ConvLSTM step. block (32,8); thread = 2 px, 16 outputs. (R11 winner)
// ---------------------------------------------------------------------------
__global__ __launch_bounds__(256, 3)
void lstm_step_kernel(const float* __restrict__ X,
                      const float* __restrict__ lw,
                      const float* __restrict__ lb,
                      const float* __restrict__ Wci,
                      const float* __restrict__ Wcf,
                      const float* __restrict__ Wco,
                      int t)
{
    __shared__ __align__(16) float sw[19 * 9 * 16];
    __shared__ __align__(16) float sp[2][4 * SPA2];
    __shared__ float sb[16];

    const int tx = threadIdx.x, ty = threadIdx.y;
    const int tid = ty * 32 + tx;
    const int bz = blockIdx.z;
    const int b = bz >> 2, kg = bz & 3;
    const int bx = blockIdx.x * LTW, by = blockIdx.y * LTH2;
    const int x0 = bx + tx * 2, y = by + ty;

    for (int i = tid; i < 19 * 144; i += 256) {
        int lo = i / 171, rest = i - lo * 171;
        int row = (lo >> 2) * NK + kg * 4 + (lo & 3);
        sw[rest * 16 + lo] = lw[row * 171 + rest];
    }
    if (tid < 16)
        sb[tid] = lb[(tid >> 2) * NK + kg * 4 + (tid & 3)];

    const int ncin = (t == 0) ? NC : (NC + NK);
    const int nb = (ncin + 3) >> 2;

    #define LSTM_SRC(c) ((c) < NC \
        ? (X + (((size_t)b * Tt + t) * NC + (c)) * HW) \
        : (g_hs + ((size_t)b * CIN_D + (t - 1) * NK + ((c) - NC)) * HW))

    #pragma unroll
    for (int cc = 0; cc < 4; cc++)
        if (cc < ncin) stage_patch16_8(sp[0] + cc * SPA2, LSTM_SRC(cc), bx, by, tid);
    CP_COMMIT();

    __syncthreads();   // sb/sw visible

    ull acc2[8][2];
    #pragma unroll
    for (int q = 0; q < 8; q++) {
        ull bv = pack2(sb[2*q], sb[2*q+1]);
        acc2[q][0] = bv; acc2[q][1] = bv;
    }

    for (int cb = 0; cb < nb; cb++) {
        int cur = cb & 1;
        CP_WAIT0();
        __syncthreads();
        if (cb + 1 < nb) {
            int cn = (cb + 1) * 4;
            #pragma unroll
            for (int cc = 0; cc < 4; cc++)
                if (cn + cc < ncin)
                    stage_patch16_8(sp[cur ^ 1] + cc * SPA2, LSTM_SRC(cn + cc), bx, by, tid);
        }
        CP_COMMIT();
        int c0 = cb * 4;
        #pragma unroll
        for (int cc = 0; cc < 4; cc++)
            if (c0 + cc < ncin)
                conv_accum_p2(acc2, sp[cur] + cc * SPA2, sw + (c0 + cc) * 144, tx, ty);
    }
    #undef LSTM_SRC

    if (y < Hh) {
        const int p = y * Ww + x0;
        float accf[16][2];
        #pragma unroll
        for (int q = 0; q < 8; q++) {
            float2 u0 = unpack2(acc2[q][0]);
            float2 u1 = unpack2(acc2[q][1]);
            accf[2*q][0] = u0.x;   accf[2*q][1] = u1.x;
            accf[2*q+1][0] = u0.y; accf[2*q+1][1] = u1.y;
        }
        #pragma unroll
        for (int kk = 0; kk < 4; kk++) {
            int k = kg * 4 + kk;
            float2 ci2 = *(const float2*)(Wci + k * HW + p);
            float2 cf2 = *(const float2*)(Wcf + k * HW + p);
            float2 co2 = *(const float2*)(Wco + k * HW + p);
            float2 cp2 = make_float2(0.f, 0.f);
            if (t != 0)
                cp2 = *(const float2*)(g_c + ((size_t)b * NK + k) * HW + p);
            float ci_[2] = {ci2.x, ci2.y}, cf_[2] = {cf2.x, cf2.y};
            float co_[2] = {co2.x, co2.y}, cp_[2] = {cp2.x, cp2.y};
            float cn_[2], h_[2];
            #pragma unroll
            for (int px = 0; px < 2; px++) {
                float cprev = cp_[px];
                float i_ = sig_(accf[kk][px]      + ci_[px] * cprev);
                float f_ = sig_(accf[4 + kk][px]  + cf_[px] * cprev);
                float cn = f_ * cprev + i_ * tanh_(accf[8 + kk][px]);
                float o_ = sig_(accf[12 + kk][px] + co_[px] * cn);
                cn_[px] = cn;
                h_[px] = o_ * tanh_(cn);
            }
            *(float2*)(g_c + ((size_t)b * NK + k) * HW + p) = make_float2(cn_[0], cn_[1]);
            *(float2*)(g_hs + ((size_t)b * CIN_D + t * NK + k) * HW + p) = make_float2(h_[0], h_[1]);
        }
    }
}

// ---------------------------------------------------------------------------
// Offset+mask conv 64 -> 27. 3 groups of 10 computed / 9 stored. (R12 winner)
// ---------------------------------------------------------------------------
__global__ __launch_bounds__(256, 3)
void offmask_kernel(const float* __restrict__ off_w,
                    const float* __restrict__ off_b,
                    const float* __restrict__ mod_w,
                    const float* __restrict__ mod_b)
{
    __shared__ __align__(16) float sw[12 * 576];
    __shared__ __align__(16) float sp[2][4 * SPA];
    __shared__ float sb[12];

    const int tx = threadIdx.x, ty = threadIdx.y;
    const int tid = ty * 16 + tx;
    const int bz = blockIdx.z;
    const int b = bz / 3, g = bz - b * 3;
    const int base = g * 9;
    const int bx = blockIdx.x * LTW, by = blockIdx.y * LTH;
    const int x0 = bx + tx * 4, y = by + ty;

    for (int i = tid; i < 12 * 576; i += 256) {
        int rest = i / 12, lo = i - rest * 12;
        int oc = base + lo;
        float v = 0.f;
        if (lo < 10 && oc < 27) {
            if (oc < 18) v = off_w[(size_t)oc * 576 + rest];
            else v = mod_w[(size_t)(oc - 18) * 576 + rest];
        }
        sw[rest * 12 + lo] = v;
    }
    if (tid < 12) {
        int oc = base + tid;
        float v = 0.f;
        if (tid < 10 && oc < 27) v = (oc < 18) ? off_b[oc] : mod_b[oc - 18];
        sb[tid] = v;
    }

    const float* xb = g_hs + (size_t)b * CIN_D * HW;

    #pragma unroll
    for (int cc = 0; cc < 4; cc++)
        stage_patch16(sp[0] + cc * SPA, xb + (size_t)cc * HW, bx, by, tid);
    CP_COMMIT();

    __syncthreads();

    ull acc2[5][4];
    #pragma unroll
    for (int q = 0; q < 5; q++) {
        ull bv = pack2(sb[2*q], sb[2*q+1]);
        #pragma unroll
        for (int px = 0; px < 4; px++) acc2[q][px] = bv;
    }

    for (int cb = 0; cb < 16; cb++) {
        int cur = cb & 1;
        CP_WAIT0();
        __syncthreads();
        if (cb + 1 < 16) {
            int cn = (cb + 1) * 4;
            #pragma unroll
            for (int cc = 0; cc < 4; cc++)
                stage_patch16(sp[cur ^ 1] + cc * SPA, xb + (size_t)(cn + cc) * HW, bx, by, tid);
        }
        CP_COMMIT();
        int c0 = cb * 4;
        #pragma unroll
        for (int cc = 0; cc < 4; cc++)
            conv_accum_o(acc2, sp[cur] + cc * SPA, sw + (c0 + cc) * 108, tx, ty);
    }

    if (y < Hh) {
        const int p = y * Ww + x0;
        #pragma unroll
        for (int lo = 0; lo < 9; lo++) {
            int oc = base + lo;
            float o4[4];
            #pragma unroll
            for (int px = 0; px < 4; px++) {
                float2 u = unpack2(acc2[lo >> 1][px]);
                o4[px] = (lo & 1) ? u.y : u.x;
            }
            if (oc >= 18) {
                #pragma unroll
                for (int px = 0; px < 4; px++) o4[px] = 2.f * sig_(o4[px]);
            }
            *(float4*)(g_om + ((size_t)b * 27 + oc) * HW + p) = *(float4*)o4;
        }
    }
}

// ---------------------------------------------------------------------------
// Modulated deformable conv. (R8 math, now 3 CTAs/SM)
// ---------------------------------------------------------------------------
__global__ __launch_bounds__(256, 3)
void deform_kernel(const float* __restrict__ def_w,
                   const float* __restrict__ def_b)
{
    __shared__ __align__(16) float swd[NK * CIN_D * 9];
    __shared__ float sb[NK];

    const int bx = blockIdx.x * 32, by = blockIdx.y * 8;
    const int b = blockIdx.z;
    const int tx = threadIdx.x, ty = threadIdx.y;
    const int tid = ty * 32 + tx;

    for (int i = tid; i < NK * CIN_D * 9; i += 256) {
        int o = i / 576, rest = i - o * 576;
        swd[rest * 16 + o] = def_w[i];
    }
    if (tid < NK) sb[tid] = def_b[tid];
    __syncthreads();

    const int x = bx + tx, y = by + ty;
    if (y >= Hh) return;
    const int p = y * Ww + x;

    const float* xb = g_hs + (size_t)b * CIN_D * HW;
    const float* om = g_om + (size_t)b * 27 * HW;

    ull acc2[8];
    #pragma unroll
    for (int q = 0; q < 8; q++) acc2[q] = pack2(sb[2*q], sb[2*q+1]);

    #pragma unroll
    for (int j = 0; j < 9; j++) {
        int ky = j / 3, kx = j - ky * 3;
        float dy = om[(2 * j) * HW + p];
        float dx = om[(2 * j + 1) * HW + p];
        float m  = om[(18 + j) * HW + p];
        float py = (float)(y - 1 + ky) + dy;
        float px_ = (float)(x - 1 + kx) + dx;
        float y0f = floorf(py), x0f = floorf(px_);
        float wy = py - y0f, wx = px_ - x0f;
        int y0 = (int)y0f, x0 = (int)x0f;
        int y1 = y0 + 1,   x1 = x0 + 1;
        float vy0 = (y0 >= 0 && y0 < Hh) ? 1.f : 0.f;
        float vy1 = (y1 >= 0 && y1 < Hh) ? 1.f : 0.f;
        float vx0 = (x0 >= 0 && x0 < Ww) ? 1.f : 0.f;
        float vx1 = (x1 >= 0 && x1 < Ww) ? 1.f : 0.f;
        int y0c = min(max(y0, 0), Hh - 1), y1c = min(max(y1, 0), Hh - 1);
        int x0c = min(max(x0, 0), Ww - 1), x1c = min(max(x1, 0), Ww - 1);
        float w00 = (1.f - wy) * (1.f - wx) * vy0 * vx0 * m;
        float w01 = (1.f - wy) * wx         * vy0 * vx1 * m;
        float w10 = wy * (1.f - wx)         * vy1 * vx0 * m;
        float w11 = wy * wx                 * vy1 * vx1 * m;
        int o00 = y0c * Ww + x0c, o01 = y0c * Ww + x1c;
        int o10 = y1c * Ww + x0c, o11 = y1c * Ww + x1c;

        #pragma unroll 4
        for (int c = 0; c < CIN_D; c++) {
            const float* pc_ = xb + (size_t)c * HW;
            float s = w00 * pc_[o00] + w01 * pc_[o01]
                    + w10 * pc_[o10] + w11 * pc_[o11];
            ull ss = pack2(s, s);
            const ulonglong2* w2 = (const ulonglong2*)(swd + (c * 9 + j) * 16);
            ulonglong2 wa = w2[0], wb = w2[1], wc2 = w2[2], wd = w2[3];
            ffma2(acc2[0], ss, wa.x); ffma2(acc2[1], ss, wa.y);
            ffma2(acc2[2], ss, wb.x); ffma2(acc2[3], ss, wb.y);
            ffma2(acc2[4], ss, wc2.x); ffma2(acc2[5], ss, wc2.y);
            ffma2(acc2[6], ss, wd.x); ffma2(acc2[7], ss, wd.y);
        }
    }

    #pragma unroll
    for (int q = 0; q < 8; q++) {
        float2 u = unpack2(acc2[q]);
        g_def[((size_t)b * NK + 2*q    ) * HW + p] = u.x;
        g_def[((size_t)b * NK + 2*q + 1) * HW + p] = u.y;
    }
}

// ---------------------------------------------------------------------------
// Output conv 16 -> 48 + pixel shuffle + clip. block (32,8), 2 px/thread,
// 3 groups of 16, 3 CTAs/SM. blockIdx.z = b*3 + g3.
// ---------------------------------------------------------------------------
__global__ __launch_bounds__(256, 3)
void outconv_kernel(const float* __restrict__ out_w,
                    const float* __restrict__ out_b,
                    float* __restrict__ out)
{
    __shared__ __align__(16) float sw[16 * 144];
    __shared__ __align__(16) float sp[2][4 * SPA2];
    __shared__ float sb[16];

    const int tx = threadIdx.x, ty = threadIdx.y;
    const int tid = ty * 32 + tx;
    const int bz = blockIdx.z;
    const int b = bz / 3, g3 = bz - b * 3;
    const int base = g3 * 16;
    const int bx = blockIdx.x * LTW, by = blockIdx.y * LTH2;
    const int x0 = bx + tx * 2, y = by + ty;

    for (int i = tid; i < 16 * 144; i += 256) {
        int lo = i / 144, rest = i - lo * 144;
        sw[rest * 16 + lo] = out_w[(size_t)(base + lo) * 144 + rest];
    }
    if (tid < 16) sb[tid] = out_b[base + tid];

    const float* xb = g_def + (size_t)b * NK * HW;

    #pragma unroll
    for (int cc = 0; cc < 4; cc++)
        stage_patch16_8(sp[0] + cc * SPA2, xb + (size_t)cc * HW, bx, by, tid);
    CP_COMMIT();

    __syncthreads();

    ull acc2[8][2];
    #pragma unroll
    for (int q = 0; q < 8; q++) {
        ull bv = pack2(sb[2*q], sb[2*q+1]);
        acc2[q][0] = bv; acc2[q][1] = bv;
    }

    for (int cb = 0; cb < 4; cb++) {
        int cur = cb & 1;
        CP_WAIT0();
        __syncthreads();
        if (cb + 1 < 4) {
            int cn = (cb + 1) * 4;
            #pragma unroll
            for (int cc = 0; cc < 4; cc++)
                stage_patch16_8(sp[cur ^ 1] + cc * SPA2, xb + (size_t)(cn + cc) * HW, bx, by, tid);
        }
        CP_COMMIT();
        int c0 = cb * 4;
        #pragma unroll
        for (int cc = 0; cc < 4; cc++)
            conv_accum_p2(acc2, sp[cur] + cc * SPA2, sw + (c0 + cc) * 144, tx, ty);
    }

    if (y < Hh) {
        #pragma unroll
        for (int lo = 0; lo < 16; lo++) {
            int oc = base + lo;
            int cch = oc >> 4, rem = oc & 15;
            int r1 = rem >> 2, r2 = rem & 3;
            float2 u = unpack2(acc2[lo >> 1][0]);
            float2 u2 = unpack2(acc2[lo >> 1][1]);
            float v0 = (lo & 1) ? u.y : u.x;
            float v1 = (lo & 1) ? u2.y : u2.x;
            v0 = fminf(fmaxf(v0, 0.f), 255.f);
            v1 = fminf(fmaxf(v1, 0.f), 255.f);
            size_t rowbase = (((size_t)b * NC + cch) * (Hh * SCALE) + (y * SCALE + r1))
                             * (size_t)(Ww * SCALE);
            out[rowbase + (x0 * SCALE + r2)] = v0;
            out[rowbase + ((x0 + 1) * SCALE + r2)] = v1;
        }
    }
}

// ---------------------------------------------------------------------------
extern "C" void kernel_launch(void* const* d_in, const int* in_sizes, int n_in,
                              void* d_out, int out_size)
{
    const float* X      = (const float*)d_in[0];
    const float* lstm_w = (const float*)d_in[1];
    const float* lstm_b = (const float*)d_in[2];
    const float* W_ci   = (const float*)d_in[3];
    const float* W_cf   = (const float*)d_in[4];
    const float* W_co   = (const float*)d_in[5];
    const float* off_w  = (const float*)d_in[6];
    const float* off_b  = (const float*)d_in[7];
    const float* mod_w  = (const float*)d_in[8];
    const float* mod_b  = (const float*)d_in[9];
    const float* def_w  = (const float*)d_in[10];
    const float* def_b  = (const float*)d_in[11];
    const float* out_w  = (const float*)d_in[12];
    const float* out_b  = (const float*)d_in[13];
    float* out = (float*)d_out;

    dim3 blk32x8(32, 8);
    dim3 grid_lstm(Ww / LTW, (Hh + LTH2 - 1) / LTH2, Bn * 4);

    dim3 blk16(16, 16);
    dim3 grid_om(Ww / LTW, (Hh + LTH - 1) / LTH, Bn * 3);

    dim3 grid_oc8(Ww / LTW, (Hh + LTH2 - 1) / LTH2, Bn * 3);

    for (int t = 0; t < Tt; t++)
        lstm_step_kernel<<<grid_lstm, blk32x8>>>(X, lstm_w, lstm_b, W_ci, W_cf, W_co, t);

    offmask_kernel<<<grid_om, blk16>>>(off_w, off_b, mod_w, mod_b);

    dim3 grid_def(Ww / 32, (Hh + 7) / 8, Bn);
    deform_kernel<<<grid_def, blk32x8>>>(def_w, def_b);

    outconv_kernel<<<grid_oc8, blk32x8>>>(out_w, out_b, out);
}

// round 14
// speedup vs baseline: 1.1198x; 1.0076x over previous
#include <cuda_runtime.h>
#include <math.h>

#define Bn 2
#define Tt 4
#define NC 3
#define NK 16
#define Hh 180
#define Ww 320
#define HW (Hh*Ww)
#define CIN_D (Tt*NK)   // 64
#define OUT_C 48
#define SCALE 4

#define LTW 64
#define LTH 16
#define SPW 72
#define SPH 18
#define SPA (SPH*SPW)
#define SPF (SPH*18)

// 8-row tiles (2 px/thread kernels)
#define LTH2 8
#define SPH2 10
#define SPA2 (SPH2*SPW)   // 720
#define SPF2 (SPH2*18)    // 180

typedef unsigned long long ull;

// Scratch (no cudaMalloc allowed)
__device__ float g_hs[Bn*CIN_D*HW];
__device__ float g_c[Bn*NK*HW];
__device__ float g_om[Bn*27*HW];
__device__ float g_def[Bn*NK*HW];

__device__ __forceinline__ float sig_(float v) {
    return __fdividef(1.f, 1.f + __expf(-v));
}
__device__ __forceinline__ float tanh_(float v) {
    float e = __expf(2.f * v);
    return 1.f - __fdividef(2.f, e + 1.f);
}

// ---- packed f32x2 helpers ----
__device__ __forceinline__ ull pack2(float lo, float hi) {
    ull r;
    asm("mov.b64 %0, {%1, %2};" : "=l"(r) : "f"(lo), "f"(hi));
    return r;
}
__device__ __forceinline__ void ffma2(ull& d, ull a, ull b) {
    asm("fma.rn.f32x2 %0, %1, %2, %0;" : "+l"(d) : "l"(a), "l"(b));
}
__device__ __forceinline__ float2 unpack2(ull v) {
    float2 f;
    asm("mov.b64 {%0, %1}, %2;" : "=f"(f.x), "=f"(f.y) : "l"(v));
    return f;
}

__device__ __forceinline__ void cp_async16(float* dst_smem, const float* src) {
    unsigned d = (unsigned)__cvta_generic_to_shared(dst_smem);
    asm volatile("cp.async.cg.shared.global [%0], [%1], 16;" :: "r"(d), "l"(src));
}
#define CP_COMMIT() asm volatile("cp.async.commit_group;" ::: "memory")
#define CP_WAIT0()  asm volatile("cp.async.wait_group 0;" ::: "memory")

// stage one conv patch (gx in [bx-4, bx+68)), 18-row version
__device__ __forceinline__ void stage_patch16(float* dst, const float* src,
                                              int bx, int by, int tid)
{
    #pragma unroll
    for (int i = tid; i < SPF; i += 256) {
        int pr = i / 18, f = i - pr * 18;
        int gy = by - 1 + pr;
        int gxf = bx - 4 + f * 4;
        float* d = dst + pr * SPW + f * 4;
        if (gy >= 0 && gy < Hh && gxf >= 0 && gxf + 4 <= Ww)
            cp_async16(d, src + gy * Ww + gxf);
        else
            *(float4*)d = make_float4(0.f, 0.f, 0.f, 0.f);
    }
}

// 10-row version for 8-row tiles
__device__ __forceinline__ void stage_patch16_8(float* dst, const float* src,
                                                int bx, int by, int tid)
{
    #pragma unroll
    for (int i = tid; i < SPF2; i += 256) {
        int pr = i / 18, f = i - pr * 18;
        int gy = by - 1 + pr;
        int gxf = bx - 4 + f * 4;
        float* d = dst + pr * SPW + f * 4;
        if (gy >= 0 && gy < Hh && gxf >= 0 && gxf + 4 <= Ww)
            cp_async16(d, src + gy * Ww + gxf);
        else
            *(float4*)d = make_float4(0.f, 0.f, 0.f, 0.f);
    }
}

// 5-pair (10-output) variant, weight stride 12 floats/tap (offmask)
__device__ __forceinline__ void conv_accum_o(ull acc2[5][4], const float* patch,
                                             const float* wc, int tx, int ty)
{
    #pragma unroll
    for (int tr = 0; tr < 3; tr++) {
        const float2* rp = (const float2*)(patch + (ty + tr) * SPW + tx * 4 + 2);
        float2 a = rp[0], b = rp[1], c = rp[2], d = rp[3];
        float v[6] = {a.y, b.x, b.y, c.x, c.y, d.x};
        ull vv[6];
        #pragma unroll
        for (int j = 0; j < 6; j++) vv[j] = pack2(v[j], v[j]);
        #pragma unroll
        for (int tc = 0; tc < 3; tc++) {
            const float* wt = wc + (tr * 3 + tc) * 12;
            ulonglong2 wa = *(const ulonglong2*)wt;
            ulonglong2 wb = *(const ulonglong2*)(wt + 4);
            ull wp4 = *(const ull*)(wt + 8);
            ull wp[5] = {wa.x, wa.y, wb.x, wb.y, wp4};
            #pragma unroll
            for (int q = 0; q < 5; q++) {
                #pragma unroll
                for (int px = 0; px < 4; px++)
                    ffma2(acc2[q][px], vv[tc + px], wp[q]);
            }
        }
    }
}

// 2-px variant (tx in [0,32)), weight stride 16; low-register version:
// each weight ulonglong2 is consumed immediately after load.
__device__ __forceinline__ void conv_accum_p2(ull acc2[8][2], const float* patch,
                                              const float* wc, int tx, int ty)
{
    #pragma unroll
    for (int tr = 0; tr < 3; tr++) {
        const float2* rp = (const float2*)(patch + (ty + tr) * SPW + tx * 2 + 2);
        float2 a = rp[0], b = rp[1], c = rp[2];
        float v[4] = {a.y, b.x, b.y, c.x};
        ull vv[4];
        #pragma unroll
        for (int j = 0; j < 4; j++) vv[j] = pack2(v[j], v[j]);
        #pragma unroll
        for (int tc = 0; tc < 3; tc++) {
            const ulonglong2* w2 = (const ulonglong2*)(wc + (tr * 3 + tc) * 16);
            #pragma unroll
            for (int h = 0; h < 4; h++) {
                ulonglong2 w = w2[h];
                ffma2(acc2[2*h][0],   vv[tc],     w.x);
                ffma2(acc2[2*h][1],   vv[tc + 1], w.x);
                ffma2(acc2[2*h+1][0], vv[tc],     w.y);
                ffma2(acc2[2*h+1][1], vv[tc + 1], w.y);
            }
        }
    }
}

// ---------------------------------------------------------------------------
// ConvLSTM step. block (32,8); thread = 2 px, 16 outputs. 4 CTAs/SM target.
// ---------------------------------------------------------------------------
__global__ __launch_bounds__(256, 4)
void lstm_step_kernel(const float* __restrict__ X,
                      const float* __restrict__ lw,
                      const float* __restrict__ lb,
                      const float* __restrict__ Wci,
                      const float* __restrict__ Wcf,
                      const float* __restrict__ Wco,
                      int t)
{
    __shared__ __align__(16) float sw[19 * 9 * 16];
    __shared__ __align__(16) float sp[2][4 * SPA2];
    __shared__ float sb[16];

    const int tx = threadIdx.x, ty = threadIdx.y;
    const int tid = ty * 32 + tx;
    const int bz = blockIdx.z;
    const int b = bz >> 2, kg = bz & 3;
    const int bx = blockIdx.x * LTW, by = blockIdx.y * LTH2;
    const int x0 = bx + tx * 2, y = by + ty;

    for (int i = tid; i < 19 * 144; i += 256) {
        int lo = i / 171, rest = i - lo * 171;
        int row = (lo >> 2) * NK + kg * 4 + (lo & 3);
        sw[rest * 16 + lo] = lw[row * 171 + rest];
    }
    if (tid < 16)
        sb[tid] = lb[(tid >> 2) * NK + kg * 4 + (tid & 3)];

    const int ncin = (t == 0) ? NC : (NC + NK);
    const int nb = (ncin + 3) >> 2;

    #define LSTM_SRC(c) ((c) < NC \
        ? (X + (((size_t)b * Tt + t) * NC + (c)) * HW) \
        : (g_hs + ((size_t)b * CIN_D + (t - 1) * NK + ((c) - NC)) * HW))

    #pragma unroll
    for (int cc = 0; cc < 4; cc++)
        if (cc < ncin) stage_patch16_8(sp[0] + cc * SPA2, LSTM_SRC(cc), bx, by, tid);
    CP_COMMIT();

    __syncthreads();   // sb/sw visible

    ull acc2[8][2];
    #pragma unroll
    for (int q = 0; q < 8; q++) {
        ull bv = pack2(sb[2*q], sb[2*q+1]);
        acc2[q][0] = bv; acc2[q][1] = bv;
    }

    for (int cb = 0; cb < nb; cb++) {
        int cur = cb & 1;
        CP_WAIT0();
        __syncthreads();
        if (cb + 1 < nb) {
            int cn = (cb + 1) * 4;
            #pragma unroll
            for (int cc = 0; cc < 4; cc++)
                if (cn + cc < ncin)
                    stage_patch16_8(sp[cur ^ 1] + cc * SPA2, LSTM_SRC(cn + cc), bx, by, tid);
        }
        CP_COMMIT();
        int c0 = cb * 4;
        #pragma unroll
        for (int cc = 0; cc < 4; cc++)
            if (c0 + cc < ncin)
                conv_accum_p2(acc2, sp[cur] + cc * SPA2, sw + (c0 + cc) * 144, tx, ty);
    }
    #undef LSTM_SRC

    if (y < Hh) {
        const int p = y * Ww + x0;
        float accf[16][2];
        #pragma unroll
        for (int q = 0; q < 8; q++) {
            float2 u0 = unpack2(acc2[q][0]);
            float2 u1 = unpack2(acc2[q][1]);
            accf[2*q][0] = u0.x;   accf[2*q][1] = u1.x;
            accf[2*q+1][0] = u0.y; accf[2*q+1][1] = u1.y;
        }
        #pragma unroll
        for (int kk = 0; kk < 4; kk++) {
            int k = kg * 4 + kk;
            float2 ci2 = *(const float2*)(Wci + k * HW + p);
            float2 cf2 = *(const float2*)(Wcf + k * HW + p);
            float2 co2 = *(const float2*)(Wco + k * HW + p);
            float2 cp2 = make_float2(0.f, 0.f);
            if (t != 0)
                cp2 = *(const float2*)(g_c + ((size_t)b * NK + k) * HW + p);
            float ci_[2] = {ci2.x, ci2.y}, cf_[2] = {cf2.x, cf2.y};
            float co_[2] = {co2.x, co2.y}, cp_[2] = {cp2.x, cp2.y};
            float cn_[2], h_[2];
            #pragma unroll
            for (int px = 0; px < 2; px++) {
                float cprev = cp_[px];
                float i_ = sig_(accf[kk][px]      + ci_[px] * cprev);
                float f_ = sig_(accf[4 + kk][px]  + cf_[px] * cprev);
                float cn = f_ * cprev + i_ * tanh_(accf[8 + kk][px]);
                float o_ = sig_(accf[12 + kk][px] + co_[px] * cn);
                cn_[px] = cn;
                h_[px] = o_ * tanh_(cn);
            }
            *(float2*)(g_c + ((size_t)b * NK + k) * HW + p) = make_float2(cn_[0], cn_[1]);
            *(float2*)(g_hs + ((size_t)b * CIN_D + t * NK + k) * HW + p) = make_float2(h_[0], h_[1]);
        }
    }
}

// ---------------------------------------------------------------------------
// Offset+mask conv 64 -> 27. 3 groups of 10 computed / 9 stored. (R12 winner)
// ---------------------------------------------------------------------------
__global__ __launch_bounds__(256, 3)
void offmask_kernel(const float* __restrict__ off_w,
                    const float* __restrict__ off_b,
                    const float* __restrict__ mod_w,
                    const float* __restrict__ mod_b)
{
    __shared__ __align__(16) float sw[12 * 576];
    __shared__ __align__(16) float sp[2][4 * SPA];
    __shared__ float sb[12];

    const int tx = threadIdx.x, ty = threadIdx.y;
    const int tid = ty * 16 + tx;
    const int bz = blockIdx.z;
    const int b = bz / 3, g = bz - b * 3;
    const int base = g * 9;
    const int bx = blockIdx.x * LTW, by = blockIdx.y * LTH;
    const int x0 = bx + tx * 4, y = by + ty;

    for (int i = tid; i < 12 * 576; i += 256) {
        int rest = i / 12, lo = i - rest * 12;
        int oc = base + lo;
        float v = 0.f;
        if (lo < 10 && oc < 27) {
            if (oc < 18) v = off_w[(size_t)oc * 576 + rest];
            else v = mod_w[(size_t)(oc - 18) * 576 + rest];
        }
        sw[rest * 12 + lo] = v;
    }
    if (tid < 12) {
        int oc = base + tid;
        float v = 0.f;
        if (tid < 10 && oc < 27) v = (oc < 18) ? off_b[oc] : mod_b[oc - 18];
        sb[tid] = v;
    }

    const float* xb = g_hs + (size_t)b * CIN_D * HW;

    #pragma unroll
    for (int cc = 0; cc < 4; cc++)
        stage_patch16(sp[0] + cc * SPA, xb + (size_t)cc * HW, bx, by, tid);
    CP_COMMIT();

    __syncthreads();

    ull acc2[5][4];
    #pragma unroll
    for (int q = 0; q < 5; q++) {
        ull bv = pack2(sb[2*q], sb[2*q+1]);
        #pragma unroll
        for (int px = 0; px < 4; px++) acc2[q][px] = bv;
    }

    for (int cb = 0; cb < 16; cb++) {
        int cur = cb & 1;
        CP_WAIT0();
        __syncthreads();
        if (cb + 1 < 16) {
            int cn = (cb + 1) * 4;
            #pragma unroll
            for (int cc = 0; cc < 4; cc++)
                stage_patch16(sp[cur ^ 1] + cc * SPA, xb + (size_t)(cn + cc) * HW, bx, by, tid);
        }
        CP_COMMIT();
        int c0 = cb * 4;
        #pragma unroll
        for (int cc = 0; cc < 4; cc++)
            conv_accum_o(acc2, sp[cur] + cc * SPA, sw + (c0 + cc) * 108, tx, ty);
    }

    if (y < Hh) {
        const int p = y * Ww + x0;
        #pragma unroll
        for (int lo = 0; lo < 9; lo++) {
            int oc = base + lo;
            float o4[4];
            #pragma unroll
            for (int px = 0; px < 4; px++) {
                float2 u = unpack2(acc2[lo >> 1][px]);
                o4[px] = (lo & 1) ? u.y : u.x;
            }
            if (oc >= 18) {
                #pragma unroll
                for (int px = 0; px < 4; px++) o4[px] = 2.f * sig_(o4[px]);
            }
            *(float4*)(g_om + ((size_t)b * 27 + oc) * HW + p) = *(float4*)o4;
        }
    }
}

// ---------------------------------------------------------------------------
// Modulated deformable conv. (R13 version, 3 CTAs/SM)
// ---------------------------------------------------------------------------
__global__ __launch_bounds__(256, 3)
void deform_kernel(const float* __restrict__ def_w,
                   const float* __restrict__ def_b)
{
    __shared__ __align__(16) float swd[NK * CIN_D * 9];
    __shared__ float sb[NK];

    const int bx = blockIdx.x * 32, by = blockIdx.y * 8;
    const int b = blockIdx.z;
    const int tx = threadIdx.x, ty = threadIdx.y;
    const int tid = ty * 32 + tx;

    for (int i = tid; i < NK * CIN_D * 9; i += 256) {
        int o = i / 576, rest = i - o * 576;
        swd[rest * 16 + o] = def_w[i];
    }
    if (tid < NK) sb[tid] = def_b[tid];
    __syncthreads();

    const int x = bx + tx, y = by + ty;
    if (y >= Hh) return;
    const int p = y * Ww + x;

    const float* xb = g_hs + (size_t)b * CIN_D * HW;
    const float* om = g_om + (size_t)b * 27 * HW;

    ull acc2[8];
    #pragma unroll
    for (int q = 0; q < 8; q++) acc2[q] = pack2(sb[2*q], sb[2*q+1]);

    #pragma unroll
    for (int j = 0; j < 9; j++) {
        int ky = j / 3, kx = j - ky * 3;
        float dy = om[(2 * j) * HW + p];
        float dx = om[(2 * j + 1) * HW + p];
        float m  = om[(18 + j) * HW + p];
        float py = (float)(y - 1 + ky) + dy;
        float px_ = (float)(x - 1 + kx) + dx;
        float y0f = floorf(py), x0f = floorf(px_);
        float wy = py - y0f, wx = px_ - x0f;
        int y0 = (int)y0f, x0 = (int)x0f;
        int y1 = y0 + 1,   x1 = x0 + 1;
        float vy0 = (y0 >= 0 && y0 < Hh) ? 1.f : 0.f;
        float vy1 = (y1 >= 0 && y1 < Hh) ? 1.f : 0.f;
        float vx0 = (x0 >= 0 && x0 < Ww) ? 1.f : 0.f;
        float vx1 = (x1 >= 0 && x1 < Ww) ? 1.f : 0.f;
        int y0c = min(max(y0, 0), Hh - 1), y1c = min(max(y1, 0), Hh - 1);
        int x0c = min(max(x0, 0), Ww - 1), x1c = min(max(x1, 0), Ww - 1);
        float w00 = (1.f - wy) * (1.f - wx) * vy0 * vx0 * m;
        float w01 = (1.f - wy) * wx         * vy0 * vx1 * m;
        float w10 = wy * (1.f - wx)         * vy1 * vx0 * m;
        float w11 = wy * wx                 * vy1 * vx1 * m;
        int o00 = y0c * Ww + x0c, o01 = y0c * Ww + x1c;
        int o10 = y1c * Ww + x0c, o11 = y1c * Ww + x1c;

        #pragma unroll 4
        for (int c = 0; c < CIN_D; c++) {
            const float* pc_ = xb + (size_t)c * HW;
            float s = w00 * pc_[o00] + w01 * pc_[o01]
                    + w10 * pc_[o10] + w11 * pc_[o11];
            ull ss = pack2(s, s);
            const ulonglong2* w2 = (const ulonglong2*)(swd + (c * 9 + j) * 16);
            ulonglong2 wa = w2[0], wb = w2[1], wc2 = w2[2], wd = w2[3];
            ffma2(acc2[0], ss, wa.x); ffma2(acc2[1], ss, wa.y);
            ffma2(acc2[2], ss, wb.x); ffma2(acc2[3], ss, wb.y);
            ffma2(acc2[4], ss, wc2.x); ffma2(acc2[5], ss, wc2.y);
            ffma2(acc2[6], ss, wd.x); ffma2(acc2[7], ss, wd.y);
        }
    }

    #pragma unroll
    for (int q = 0; q < 8; q++) {
        float2 u = unpack2(acc2[q]);
        g_def[((size_t)b * NK + 2*q    ) * HW + p] = u.x;
        g_def[((size_t)b * NK + 2*q + 1) * HW + p] = u.y;
    }
}

// ---------------------------------------------------------------------------
// Output conv 16 -> 48 + pixel shuffle + clip. (R13 version, 2px, 3 CTAs/SM)
// ---------------------------------------------------------------------------
__global__ __launch_bounds__(256, 3)
void outconv_kernel(const float* __restrict__ out_w,
                    const float* __restrict__ out_b,
                    float* __restrict__ out)
{
    __shared__ __align__(16) float sw[16 * 144];
    __shared__ __align__(16) float sp[2][4 * SPA2];
    __shared__ float sb[16];

    const int tx = threadIdx.x, ty = threadIdx.y;
    const int tid = ty * 32 + tx;
    const int bz = blockIdx.z;
    const int b = bz / 3, g3 = bz - b * 3;
    const int base = g3 * 16;
    const int bx = blockIdx.x * LTW, by = blockIdx.y * LTH2;
    const int x0 = bx + tx * 2, y = by + ty;

    for (int i = tid; i < 16 * 144; i += 256) {
        int lo = i / 144, rest = i - lo * 144;
        sw[rest * 16 + lo] = out_w[(size_t)(base + lo) * 144 + rest];
    }
    if (tid < 16) sb[tid] = out_b[base + tid];

    const float* xb = g_def + (size_t)b * NK * HW;

    #pragma unroll
    for (int cc = 0; cc < 4; cc++)
        stage_patch16_8(sp[0] + cc * SPA2, xb + (size_t)cc * HW, bx, by, tid);
    CP_COMMIT();

    __syncthreads();

    ull acc2[8][2];
    #pragma unroll
    for (int q = 0; q < 8; q++) {
        ull bv = pack2(sb[2*q], sb[2*q+1]);
        acc2[q][0] = bv; acc2[q][1] = bv;
    }

    for (int cb = 0; cb < 4; cb++) {
        int cur = cb & 1;
        CP_WAIT0();
        __syncthreads();
        if (cb + 1 < 4) {
            int cn = (cb + 1) * 4;
            #pragma unroll
            for (int cc = 0; cc < 4; cc++)
                stage_patch16_8(sp[cur ^ 1] + cc * SPA2, xb + (size_t)(cn + cc) * HW, bx, by, tid);
        }
        CP_COMMIT();
        int c0 = cb * 4;
        #pragma unroll
        for (int cc = 0; cc < 4; cc++)
            conv_accum_p2(acc2, sp[cur] + cc * SPA2, sw + (c0 + cc) * 144, tx, ty);
    }

    if (y < Hh) {
        #pragma unroll
        for (int lo = 0; lo < 16; lo++) {
            int oc = base + lo;
            int cch = oc >> 4, rem = oc & 15;
            int r1 = rem >> 2, r2 = rem & 3;
            float2 u = unpack2(acc2[lo >> 1][0]);
            float2 u2 = unpack2(acc2[lo >> 1][1]);
            float v0 = (lo & 1) ? u.y : u.x;
            float v1 = (lo & 1) ? u2.y : u2.x;
            v0 = fminf(fmaxf(v0, 0.f), 255.f);
            v1 = fminf(fmaxf(v1, 0.f), 255.f);
            size_t rowbase = (((size_t)b * NC + cch) * (Hh * SCALE) + (y * SCALE + r1))
                             * (size_t)(Ww * SCALE);
            out[rowbase + (x0 * SCALE + r2)] = v0;
            out[rowbase + ((x0 + 1) * SCALE + r2)] = v1;
        }
    }
}

// ---------------------------------------------------------------------------
extern "C" void kernel_launch(void* const* d_in, const int* in_sizes, int n_in,
                              void* d_out, int out_size)
{
    const float* X      = (const float*)d_in[0];
    const float* lstm_w = (const float*)d_in[1];
    const float* lstm_b = (const float*)d_in[2];
    const float* W_ci   = (const float*)d_in[3];
    const float* W_cf   = (const float*)d_in[4];
    const float* W_co   = (const float*)d_in[5];
    const float* off_w  = (const float*)d_in[6];
    const float* off_b  = (const float*)d_in[7];
    const float* mod_w  = (const float*)d_in[8];
    const float* mod_b  = (const float*)d_in[9];
    const float* def_w  = (const float*)d_in[10];
    const float* def_b  = (const float*)d_in[11];
    const float* out_w  = (const float*)d_in[12];
    const float* out_b  = (const float*)d_in[13];
    float* out = (float*)d_out;

    dim3 blk32x8(32, 8);
    dim3 grid_lstm(Ww / LTW, (Hh + LTH2 - 1) / LTH2, Bn * 4);

    dim3 blk16(16, 16);
    dim3 grid_om(Ww / LTW, (Hh + LTH - 1) / LTH, Bn * 3);

    dim3 grid_oc8(Ww / LTW, (Hh + LTH2 - 1) / LTH2, Bn * 3);

    for (int t = 0; t < Tt; t++)
        lstm_step_kernel<<<grid_lstm, blk32x8>>>(X, lstm_w, lstm_b, W_ci, W_cf, W_co, t);

    offmask_kernel<<<grid_om, blk16>>>(off_w, off_b, mod_w, mod_b);

    dim3 grid_def(Ww / 32, (Hh + 7) / 8, Bn);
    deform_kernel<<<grid_def, blk32x8>>>(def_w, def_b);

    outconv_kernel<<<grid_oc8, blk32x8>>>(out_w, out_b, out);
}